// round 12
// baseline (speedup 1.0000x reference)
#include <cuda_runtime.h>
#include <math.h>

#define NN 100000
#define NE 1600000
#define NG 256
#define DH 128
#define DOUT 8
#define NLAYERS 4

// Scratch (no allocation allowed) — static device globals.
__device__ float g_pooled[(size_t)NN * DH];
__device__ float g_tmp[(size_t)NN * DH];
__device__ int   g_deg[NN];
__device__ int   g_rowptr[NN + 1];
__device__ int   g_cursor[NN];
__device__ int   g_bsums[256];
__device__ int   g_csr_src[NE];
__device__ float g_csr_mask[NE];

// ---------------------------------------------------------------------------
// f32x2 packed helpers (sm_10x packed fp32 pipe)
// ---------------------------------------------------------------------------
__device__ __forceinline__ unsigned long long pk2(float x) {
    unsigned long long r; unsigned int u = __float_as_uint(x);
    asm("mov.b64 %0, {%1, %1};" : "=l"(r) : "r"(u));
    return r;
}
__device__ __forceinline__ unsigned long long fma2(unsigned long long a,
                                                   unsigned long long b,
                                                   unsigned long long c) {
    unsigned long long d;
    asm("fma.rn.f32x2 %0, %1, %2, %3;" : "=l"(d) : "l"(a), "l"(b), "l"(c));
    return d;
}
__device__ __forceinline__ float2 up2(unsigned long long v) {
    unsigned int lo, hi;
    asm("mov.b64 {%0, %1}, %2;" : "=r"(lo), "=r"(hi) : "l"(v));
    return make_float2(__uint_as_float(lo), __uint_as_float(hi));
}

// ---------------------------------------------------------------------------
// Y[N,128] = act(X[N,128] @ W^T + b), W[128,128] row-major (out,in)
// 256 threads; block tile 64 rows x 128 cols.
// Smem: XsT[k][row] (transposed X, 128x64) + Ws[k][j] (transposed W, 128x128).
// Thread (tx=tid&31, ty=tid>>5): cols tx*4..+3, row-pairs ty*8+2p (p=0..3),
// accumulators are f32x2 packed over the row pair.
// ---------------------------------------------------------------------------
template<bool RELU>
__global__ void __launch_bounds__(256, 2)
gemm128(const float* __restrict__ X, const float* __restrict__ W,
        const float* __restrict__ bias, float* __restrict__ Y, int N)
{
    extern __shared__ float smem[];
    float* XsT = smem;                 // 128*64 floats (32KB)
    float* Ws  = smem + 128 * 64;      // 128*128 floats (64KB), Ws[k*128+j]=W[j][k]

    const int tid = threadIdx.x;
    const int tx  = tid & 31;
    const int ty  = tid >> 5;
    const int row0 = blockIdx.x * 64;

    // Fill W transposed: lanes vary j (fast store index) -> conflict-free STS
    for (int i = tid; i < 128 * 32; i += 256) {
        int j  = i & 127;
        int kk = i >> 7;           // 0..31
        float4 w = reinterpret_cast<const float4*>(W)[j * 32 + kk];
        int k4 = kk << 2;
        Ws[(k4 + 0) * 128 + j] = w.x;
        Ws[(k4 + 1) * 128 + j] = w.y;
        Ws[(k4 + 2) * 128 + j] = w.z;
        Ws[(k4 + 3) * 128 + j] = w.w;
    }
    // Fill X transposed: lanes vary r (fast store index) -> conflict-free STS
    for (int i = tid; i < 64 * 32; i += 256) {
        int r  = i & 63;
        int kk = i >> 6;           // 0..31
        int row = row0 + r;
        float4 v = make_float4(0.f, 0.f, 0.f, 0.f);
        if (row < N)
            v = reinterpret_cast<const float4*>(X)[(size_t)row * 32 + kk];
        int k4 = kk << 2;
        XsT[(k4 + 0) * 64 + r] = v.x;
        XsT[(k4 + 1) * 64 + r] = v.y;
        XsT[(k4 + 2) * 64 + r] = v.z;
        XsT[(k4 + 3) * 64 + r] = v.w;
    }
    __syncthreads();

    unsigned long long acc[4][4];
#pragma unroll
    for (int p = 0; p < 4; p++)
#pragma unroll
        for (int c = 0; c < 4; c++) acc[p][c] = 0ull;

    const float4* Ws4 = reinterpret_cast<const float4*>(Ws);
    const unsigned long long* XsT2 =
        reinterpret_cast<const unsigned long long*>(XsT);

#pragma unroll 8
    for (int k = 0; k < 128; k++) {
        float4 b = Ws4[k * 32 + tx];                   // conflict-free LDS.128
        unsigned long long bb0 = pk2(b.x);
        unsigned long long bb1 = pk2(b.y);
        unsigned long long bb2 = pk2(b.z);
        unsigned long long bb3 = pk2(b.w);
        unsigned long long a0 = XsT2[k * 32 + ty * 4 + 0];  // broadcast LDS.64
        unsigned long long a1 = XsT2[k * 32 + ty * 4 + 1];
        unsigned long long a2 = XsT2[k * 32 + ty * 4 + 2];
        unsigned long long a3 = XsT2[k * 32 + ty * 4 + 3];
        acc[0][0] = fma2(a0, bb0, acc[0][0]);
        acc[0][1] = fma2(a0, bb1, acc[0][1]);
        acc[0][2] = fma2(a0, bb2, acc[0][2]);
        acc[0][3] = fma2(a0, bb3, acc[0][3]);
        acc[1][0] = fma2(a1, bb0, acc[1][0]);
        acc[1][1] = fma2(a1, bb1, acc[1][1]);
        acc[1][2] = fma2(a1, bb2, acc[1][2]);
        acc[1][3] = fma2(a1, bb3, acc[1][3]);
        acc[2][0] = fma2(a2, bb0, acc[2][0]);
        acc[2][1] = fma2(a2, bb1, acc[2][1]);
        acc[2][2] = fma2(a2, bb2, acc[2][2]);
        acc[2][3] = fma2(a2, bb3, acc[2][3]);
        acc[3][0] = fma2(a3, bb0, acc[3][0]);
        acc[3][1] = fma2(a3, bb1, acc[3][1]);
        acc[3][2] = fma2(a3, bb2, acc[3][2]);
        acc[3][3] = fma2(a3, bb3, acc[3][3]);
    }

    float4 bb = reinterpret_cast<const float4*>(bias)[tx];
#pragma unroll
    for (int p = 0; p < 4; p++) {
        float2 c0 = up2(acc[p][0]);
        float2 c1 = up2(acc[p][1]);
        float2 c2 = up2(acc[p][2]);
        float2 c3 = up2(acc[p][3]);
        int row = row0 + ty * 8 + 2 * p;
        if (row < N) {
            float4 o = make_float4(c0.x + bb.x, c1.x + bb.y, c2.x + bb.z, c3.x + bb.w);
            if (RELU) { o.x = fmaxf(o.x, 0.f); o.y = fmaxf(o.y, 0.f);
                        o.z = fmaxf(o.z, 0.f); o.w = fmaxf(o.w, 0.f); }
            reinterpret_cast<float4*>(Y)[(size_t)row * 32 + tx] = o;
        }
        if (row + 1 < N) {
            float4 o = make_float4(c0.y + bb.x, c1.y + bb.y, c2.y + bb.z, c3.y + bb.w);
            if (RELU) { o.x = fmaxf(o.x, 0.f); o.y = fmaxf(o.y, 0.f);
                        o.z = fmaxf(o.z, 0.f); o.w = fmaxf(o.w, 0.f); }
            reinterpret_cast<float4*>(Y)[(size_t)(row + 1) * 32 + tx] = o;
        }
    }
}

// ---------------------------------------------------------------------------
// CSR build: degree count -> block scan -> fill
// ---------------------------------------------------------------------------
__global__ void count_deg(const int* __restrict__ ei, int* __restrict__ deg)
{
    int e = blockIdx.x * blockDim.x + threadIdx.x;
    if (e < NE) atomicAdd(&deg[ei[e]], 1);
}

#define SCAN_B 512
__global__ void scan1(const int* __restrict__ deg, int* __restrict__ rowptr,
                      int* __restrict__ bsums)
{
    __shared__ int sh[SCAN_B];
    int tid = threadIdx.x;
    int i = blockIdx.x * SCAN_B + tid;
    int v = (i < NN) ? deg[i] : 0;
    sh[tid] = v;
    __syncthreads();
#pragma unroll
    for (int off = 1; off < SCAN_B; off <<= 1) {
        int t = (tid >= off) ? sh[tid - off] : 0;
        __syncthreads();
        sh[tid] += t;
        __syncthreads();
    }
    if (i < NN) rowptr[i] = sh[tid] - v;      // exclusive within block
    if (tid == SCAN_B - 1) bsums[blockIdx.x] = sh[tid];
}

__global__ void scan2(int* __restrict__ bsums, int nb)
{
    __shared__ int sh[256];
    int tid = threadIdx.x;
    int v = (tid < nb) ? bsums[tid] : 0;
    sh[tid] = v;
    __syncthreads();
#pragma unroll
    for (int off = 1; off < 256; off <<= 1) {
        int t = (tid >= off) ? sh[tid - off] : 0;
        __syncthreads();
        sh[tid] += t;
        __syncthreads();
    }
    if (tid < nb) bsums[tid] = sh[tid] - v;   // exclusive
}

__global__ void scan3(int* __restrict__ rowptr, const int* __restrict__ bsums,
                      int* __restrict__ cursor)
{
    int i = blockIdx.x * SCAN_B + threadIdx.x;
    if (i < NN) {
        int r = rowptr[i] + bsums[blockIdx.x];
        rowptr[i] = r;
        cursor[i] = r;
    }
    if (i == 0) rowptr[NN] = NE;
}

__global__ void fill_csr(const int* __restrict__ ei, const float* __restrict__ mask,
                         int* __restrict__ cursor, int* __restrict__ csr_src,
                         float* __restrict__ csr_mask)
{
    int e = blockIdx.x * blockDim.x + threadIdx.x;
    if (e >= NE) return;
    int dst = ei[e];
    int src = ei[NE + e];
    int p = atomicAdd(&cursor[dst], 1);
    csr_src[p]  = src;
    csr_mask[p] = mask[e];
}

// ---------------------------------------------------------------------------
// pooled[n] = sum_{e in CSR(n)} mask_e * h[src_e] + (1+eps[l]) * h[n]
// One warp per node; lane = float4 chunk of the 128-dim feature.
// ---------------------------------------------------------------------------
__global__ void aggregate(const float* __restrict__ h, const int* __restrict__ rowptr,
                          const int* __restrict__ csr_src, const float* __restrict__ csr_mask,
                          const float* __restrict__ eps, int l, float* __restrict__ pooled)
{
    int g = (blockIdx.x * blockDim.x + threadIdx.x) >> 5;
    int lane = threadIdx.x & 31;
    if (g >= NN) return;
    int beg = rowptr[g];
    int end = rowptr[g + 1];
    const float4* h4 = reinterpret_cast<const float4*>(h);

    float4 acc = make_float4(0.f, 0.f, 0.f, 0.f);
    int j = beg;
    for (; j + 1 < end; j += 2) {
        int   s0 = csr_src[j],   s1 = csr_src[j + 1];
        float m0 = csr_mask[j],  m1 = csr_mask[j + 1];
        float4 v0 = h4[(size_t)s0 * 32 + lane];
        float4 v1 = h4[(size_t)s1 * 32 + lane];
        acc.x += m0 * v0.x + m1 * v1.x;
        acc.y += m0 * v0.y + m1 * v1.y;
        acc.z += m0 * v0.z + m1 * v1.z;
        acc.w += m0 * v0.w + m1 * v1.w;
    }
    if (j < end) {
        int s0 = csr_src[j];
        float m0 = csr_mask[j];
        float4 v0 = h4[(size_t)s0 * 32 + lane];
        acc.x += m0 * v0.x; acc.y += m0 * v0.y;
        acc.z += m0 * v0.z; acc.w += m0 * v0.w;
    }
    float s = 1.f + eps[l];
    float4 hv = h4[(size_t)g * 32 + lane];
    acc.x += s * hv.x; acc.y += s * hv.y;
    acc.z += s * hv.z; acc.w += s * hv.w;
    reinterpret_cast<float4*>(pooled)[(size_t)g * 32 + lane] = acc;
}

// pooled_sum[g] += sum over 5 embeds of nodes in graph g (batch is sorted)
__global__ void pool_batch(const float* __restrict__ embs, const int* __restrict__ batch,
                           float* __restrict__ ps)
{
    const int j = threadIdx.x;                 // column 0..127
    const int start = blockIdx.x * 128;
    int end = start + 128;
    if (end > NN) end = NN;
    if (start >= NN) return;

    const size_t EMB = (size_t)NN * DH;
    int gc = batch[start];
    float acc = 0.f;
    for (int i = start; i < end; i++) {
        int g = batch[i];
        if (g != gc) {
            atomicAdd(&ps[(size_t)gc * 128 + j], acc);
            acc = 0.f;
            gc = g;
        }
        size_t off = (size_t)i * 128 + j;
        float s = embs[off] + embs[EMB + off] + embs[2 * EMB + off]
                + embs[3 * EMB + off] + embs[4 * EMB + off];
        acc += s;
    }
    atomicAdd(&ps[(size_t)gc * 128 + j], acc);
}

// Head: lin1 = relu(ps @ W1^T + b1); lin1d = lin1; lin2 = lin1 @ W2^T + b2; softmax
__global__ void head(const float* __restrict__ ps,
                     const float* __restrict__ W1, const float* __restrict__ b1,
                     const float* __restrict__ W2, const float* __restrict__ b2,
                     float* __restrict__ lin1, float* __restrict__ lin1d,
                     float* __restrict__ lin2, float* __restrict__ soft)
{
    __shared__ float row[128];
    __shared__ float l1s[128];
    __shared__ float l2s[8];
    const int g = blockIdx.x;
    const int j = threadIdx.x;

    row[j] = ps[(size_t)g * 128 + j];
    __syncthreads();

    float a = b1[j];
#pragma unroll 8
    for (int k = 0; k < 128; k++) a += row[k] * W1[j * 128 + k];
    a = fmaxf(a, 0.f);
    l1s[j] = a;
    lin1[(size_t)g * 128 + j] = a;
    lin1d[(size_t)g * 128 + j] = a;
    __syncthreads();

    if (j < 8) {
        float s = b2[j];
#pragma unroll 8
        for (int k = 0; k < 128; k++) s += l1s[k] * W2[j * 128 + k];
        lin2[(size_t)g * 8 + j] = s;
        l2s[j] = s;
    }
    __syncthreads();
    if (j == 0) {
        float mx = l2s[0];
#pragma unroll
        for (int q = 1; q < 8; q++) mx = fmaxf(mx, l2s[q]);
        float ex[8]; float sum = 0.f;
#pragma unroll
        for (int q = 0; q < 8; q++) { ex[q] = expf(l2s[q] - mx); sum += ex[q]; }
        float inv = 1.f / sum;
#pragma unroll
        for (int q = 0; q < 8; q++) soft[(size_t)g * 8 + q] = ex[q] * inv;
    }
}

extern "C" void kernel_launch(void* const* d_in, const int* in_sizes, int n_in,
                              void* d_out, int out_size)
{
    const float* x     = (const float*)d_in[0];
    const int*   ei    = (const int*)  d_in[1];
    const float* mask  = (const float*)d_in[2];
    const int*   batch = (const int*)  d_in[3];
    const float* eps   = (const float*)d_in[4];
    const float* Wf    = (const float*)d_in[5];
    const float* bf    = (const float*)d_in[6];
    const float* gW    = (const float*)d_in[7];   // [4][2][128][128]
    const float* gb    = (const float*)d_in[8];   // [4][2][128]
    const float* W1    = (const float*)d_in[9];
    const float* b1    = (const float*)d_in[10];
    const float* W2    = (const float*)d_in[11];
    const float* b2    = (const float*)d_in[12];

    float* out  = (float*)d_out;
    const size_t EMB = (size_t)NN * DH;
    float* embs = out;                       // [5][NN][128]
    float* ps   = out + 5 * EMB;             // [256][128]
    float* l1   = ps + (size_t)NG * DH;
    float* l1d  = l1 + (size_t)NG * DH;
    float* l2   = l1d + (size_t)NG * DH;
    float* sm   = l2 + (size_t)NG * DOUT;

    float *pooled = nullptr, *tmp = nullptr, *csr_mask = nullptr;
    int *deg = nullptr, *rowptr = nullptr, *cursor = nullptr, *bsums = nullptr, *csr_src = nullptr;
    cudaGetSymbolAddress((void**)&pooled,   g_pooled);
    cudaGetSymbolAddress((void**)&tmp,      g_tmp);
    cudaGetSymbolAddress((void**)&deg,      g_deg);
    cudaGetSymbolAddress((void**)&rowptr,   g_rowptr);
    cudaGetSymbolAddress((void**)&cursor,   g_cursor);
    cudaGetSymbolAddress((void**)&bsums,    g_bsums);
    cudaGetSymbolAddress((void**)&csr_src,  g_csr_src);
    cudaGetSymbolAddress((void**)&csr_mask, g_csr_mask);

    const int SMEM = (128 * 64 + 128 * 128) * (int)sizeof(float);  // 96 KB
    cudaFuncSetAttribute(gemm128<false>, cudaFuncAttributeMaxDynamicSharedMemorySize, SMEM);
    cudaFuncSetAttribute(gemm128<true>,  cudaFuncAttributeMaxDynamicSharedMemorySize, SMEM);

    const int GEMM_BLOCKS = (NN + 63) / 64;       // 1563
    const int SCAN_BLOCKS = (NN + SCAN_B - 1) / SCAN_B;  // 196
    const int EDGE_BLOCKS = (NE + 255) / 256;
    const int AGG_BLOCKS  = (NN * 32 + 255) / 256;
    const int POOL_BLOCKS = (NN + 127) / 128;

    // zero pooled_sum region (d_out is poisoned) + degree histogram
    cudaMemsetAsync(ps, 0, (size_t)NG * DH * sizeof(float), 0);
    cudaMemsetAsync(deg, 0, (size_t)NN * sizeof(int), 0);

    // CSR build (reused across all 4 layers)
    count_deg<<<EDGE_BLOCKS, 256>>>(ei, deg);
    scan1<<<SCAN_BLOCKS, SCAN_B>>>(deg, rowptr, bsums);
    scan2<<<1, 256>>>(bsums, SCAN_BLOCKS);
    scan3<<<SCAN_BLOCKS, SCAN_B>>>(rowptr, bsums, cursor);
    fill_csr<<<EDGE_BLOCKS, 256>>>(ei, mask, cursor, csr_src, csr_mask);

    // first linear (NO relu)
    gemm128<false><<<GEMM_BLOCKS, 256, SMEM>>>(x, Wf, bf, embs, NN);

    for (int l = 0; l < NLAYERS; l++) {
        const float* h = embs + (size_t)l * EMB;
        aggregate<<<AGG_BLOCKS, 256>>>(h, rowptr, csr_src, csr_mask, eps, l, pooled);
        gemm128<true><<<GEMM_BLOCKS, 256, SMEM>>>(
            pooled, gW + (size_t)(l * 2 + 0) * 128 * 128, gb + (size_t)(l * 2 + 0) * 128,
            tmp, NN);
        gemm128<true><<<GEMM_BLOCKS, 256, SMEM>>>(
            tmp, gW + (size_t)(l * 2 + 1) * 128 * 128, gb + (size_t)(l * 2 + 1) * 128,
            embs + (size_t)(l + 1) * EMB, NN);
    }

    pool_batch<<<POOL_BLOCKS, 128>>>(embs, batch, ps);
    head<<<NG, 128>>>(ps, W1, b1, W2, b2, l1, l1d, l2, sm);
}

// round 14
// speedup vs baseline: 1.1345x; 1.1345x over previous
#include <cuda_runtime.h>
#include <cuda_bf16.h>
#include <math.h>

#define NN 100000
#define NE 1600000
#define NG 256
#define DH 128
#define DOUT 8
#define NLAYERS 4

// Scratch (no allocation allowed) — static device globals.
__device__ float g_pooled[(size_t)NN * DH];
__device__ float g_tmp[(size_t)NN * DH];
__device__ int   g_deg[NN];
__device__ int   g_rowptr[NN + 1];
__device__ int   g_cursor[NN];
__device__ int   g_bsums[256];
__device__ int   g_csr_src[NE];
__device__ float g_csr_mask[NE];

// Weight images: per weight 69632 B = hi[128 rows x 272B] + lo[same]
#define W_PITCH   272              // 136 bf16 per row (16B*17 -> ldmatrix conflict-free)
#define W_HALF    34816            // 128 * 272
#define W_STRIDE  69632
__device__ __align__(16) unsigned char g_wimg[9 * W_STRIDE];

// ===========================================================================
// helpers
// ===========================================================================
__device__ __forceinline__ unsigned smem_u32(const void* p) {
    unsigned a;
    asm("{ .reg .u64 t; cvta.to.shared.u64 t, %1; cvt.u32.u64 %0, t; }"
        : "=r"(a) : "l"(p));
    return a;
}

#define LDSM4(d, addr) \
    asm volatile("ldmatrix.sync.aligned.m8n8.x4.shared.b16 {%0,%1,%2,%3}, [%4];" \
        : "=r"((d)[0]), "=r"((d)[1]), "=r"((d)[2]), "=r"((d)[3]) : "r"(addr))

#define MMA16816(c, a, b0, b1) \
    asm volatile("mma.sync.aligned.m16n8k16.row.col.f32.bf16.bf16.f32 " \
        "{%0,%1,%2,%3}, {%4,%5,%6,%7}, {%8,%9}, {%0,%1,%2,%3};" \
        : "+f"((c)[0]), "+f"((c)[1]), "+f"((c)[2]), "+f"((c)[3]) \
        : "r"((a)[0]), "r"((a)[1]), "r"((a)[2]), "r"((a)[3]), "r"(b0), "r"(b1))

// Convert 8 fp32 -> packed bf16 hi (uint4) and bf16 lo (uint4)
__device__ __forceinline__ void cvt8(const float* f, uint4& hv, uint4& lv) {
    __nv_bfloat162 hp[4], lp[4];
#pragma unroll
    for (int i = 0; i < 4; i++) {
        __nv_bfloat16 h0 = __float2bfloat16_rn(f[2 * i]);
        __nv_bfloat16 h1 = __float2bfloat16_rn(f[2 * i + 1]);
        float l0 = f[2 * i]     - __bfloat162float(h0);
        float l1 = f[2 * i + 1] - __bfloat162float(h1);
        hp[i].x = h0; hp[i].y = h1;
        lp[i].x = __float2bfloat16_rn(l0);
        lp[i].y = __float2bfloat16_rn(l1);
    }
    hv.x = *reinterpret_cast<unsigned*>(&hp[0]);
    hv.y = *reinterpret_cast<unsigned*>(&hp[1]);
    hv.z = *reinterpret_cast<unsigned*>(&hp[2]);
    hv.w = *reinterpret_cast<unsigned*>(&hp[3]);
    lv.x = *reinterpret_cast<unsigned*>(&lp[0]);
    lv.y = *reinterpret_cast<unsigned*>(&lp[1]);
    lv.z = *reinterpret_cast<unsigned*>(&lp[2]);
    lv.w = *reinterpret_cast<unsigned*>(&lp[3]);
}

// ---------------------------------------------------------------------------
// Weight prep: split 9 W matrices into bf16 hi/lo padded-row images.
// Block b handles weight b: 0 = W_first, 1+2l+s = gin_W[l][s].
// ---------------------------------------------------------------------------
__global__ void prep_weights(const float* __restrict__ Wf, const float* __restrict__ gW,
                             unsigned char* __restrict__ wimg)
{
    int b = blockIdx.x;
    const float* W = (b == 0) ? Wf : (gW + (size_t)(b - 1) * 128 * 128);
    unsigned char* hi = wimg + (size_t)b * W_STRIDE;
    unsigned char* lo = hi + W_HALF;
    for (int g = threadIdx.x; g < 2048; g += blockDim.x) {
        int r  = g >> 4;
        int k0 = (g & 15) << 3;
        float f[8];
#pragma unroll
        for (int q = 0; q < 8; q++) f[q] = W[r * 128 + k0 + q];
        uint4 hv, lv;
        cvt8(f, hv, lv);
        unsigned off = (unsigned)r * W_PITCH + (unsigned)k0 * 2;
        *reinterpret_cast<uint4*>(hi + off) = hv;
        *reinterpret_cast<uint4*>(lo + off) = lv;
    }
}

// ---------------------------------------------------------------------------
// Tensor-core GEMM via mma.sync (bf16x3 emulated fp32):
//   Y[N,128] = act(X[N,128] @ W^T + b)
// CTA: 128-row tile, 256 threads (8 warps); warp w -> rows w*16..w*16+15, all 128 cols.
// Dyn smem (139264 B): Ah[0,34816) Al[+34816) Bh[69632) Bl[104448).
// Row pitch 272 B => ldmatrix 8-row pointers hit distinct bank groups.
// ---------------------------------------------------------------------------
template<bool RELU>
__global__ void __launch_bounds__(256)
gemm_tc(const float* __restrict__ X, const unsigned char* __restrict__ wimg_tile,
        const float* __restrict__ bias, float* __restrict__ Y, int Nrows)
{
    extern __shared__ char sm[];
    char* Ah = sm;
    char* Al = sm + 34816;
    char* Bh = sm + 69632;
    float* stage = reinterpret_cast<float*>(sm);   // 128 x 132 fp32 (post-MMA)

    __shared__ float s_bias[128];

    const int tid  = threadIdx.x;
    const int wid  = tid >> 5;
    const int lane = tid & 31;
    const int row0 = blockIdx.x * 128;

    if (tid < 128) s_bias[tid] = bias[tid];

    // Copy weight hi/lo images (already split + padded) — 68KB linear, coalesced.
    {
        const uint4* wsrc = reinterpret_cast<const uint4*>(wimg_tile);
        uint4* bdst = reinterpret_cast<uint4*>(Bh);
        for (int i = tid; i < W_STRIDE / 16; i += 256) bdst[i] = wsrc[i];
    }
    // Load + split X tile into Ah/Al.
    for (int g = tid; g < 2048; g += 256) {
        int r  = g >> 4;
        int k0 = (g & 15) << 3;
        int row = row0 + r;
        float f[8];
        if (row < Nrows) {
            float4 v0 = reinterpret_cast<const float4*>(X)[(size_t)row * 32 + (k0 >> 2)];
            float4 v1 = reinterpret_cast<const float4*>(X)[(size_t)row * 32 + (k0 >> 2) + 1];
            f[0] = v0.x; f[1] = v0.y; f[2] = v0.z; f[3] = v0.w;
            f[4] = v1.x; f[5] = v1.y; f[6] = v1.z; f[7] = v1.w;
        } else {
#pragma unroll
            for (int q = 0; q < 8; q++) f[q] = 0.f;
        }
        uint4 hv, lv;
        cvt8(f, hv, lv);
        unsigned off = (unsigned)r * W_PITCH + (unsigned)k0 * 2;
        *reinterpret_cast<uint4*>(Ah + off) = hv;
        *reinterpret_cast<uint4*>(Al + off) = lv;
    }
    __syncthreads();

    // Fragment base addresses.
    // A (16x16 per warp per k-step): lanes 0-7 rows 0-7 @k0, 8-15 rows 8-15 @k0,
    //   16-23 rows 0-7 @k0+8, 24-31 rows 8-15 @k0+8  -> regs a0..a3 match mma A frag.
    unsigned aBaseH = smem_u32(Ah)
                    + (unsigned)(wid * 16 + (lane & 15)) * W_PITCH
                    + (unsigned)(((lane >> 4) & 1) * 16);
    unsigned aBaseL = aBaseH + 34816;
    // B (two n-tiles x k16): lanes 0-7: rows nt*8+j @k0 (b0 of nt); 8-15: same rows @k0+8 (b1);
    //   16-23: rows (nt+1)*8+j @k0; 24-31: @k0+8.
    unsigned bRowOff = (unsigned)((((lane >> 4) & 1) * 8 + (lane & 7)) * W_PITCH
                                  + ((lane >> 3) & 1) * 16);
    unsigned bBaseH = smem_u32(Bh) + bRowOff;
    unsigned bBaseL = bBaseH + 34816;

    float acc[16][4];
#pragma unroll
    for (int n = 0; n < 16; n++)
#pragma unroll
        for (int q = 0; q < 4; q++) acc[n][q] = 0.f;

#pragma unroll
    for (int ks = 0; ks < 8; ks++) {
        unsigned ah[4], al[4];
        LDSM4(ah, aBaseH + ks * 32);
        LDSM4(al, aBaseL + ks * 32);
#pragma unroll
        for (int np = 0; np < 8; np++) {          // n-tile pair (2*np, 2*np+1)
            unsigned bh[4], bl[4];
            unsigned boff = (unsigned)(np * 16 * W_PITCH + ks * 32);
            LDSM4(bh, bBaseH + boff);
            LDSM4(bl, bBaseL + boff);
            MMA16816(acc[2 * np],     ah, bh[0], bh[1]);
            MMA16816(acc[2 * np],     ah, bl[0], bl[1]);
            MMA16816(acc[2 * np],     al, bh[0], bh[1]);
            MMA16816(acc[2 * np + 1], ah, bh[2], bh[3]);
            MMA16816(acc[2 * np + 1], ah, bl[2], bl[3]);
            MMA16816(acc[2 * np + 1], al, bh[2], bh[3]);
        }
    }
    __syncthreads();   // done reading A/B smem; reuse as stage

    // Epilogue: C frag (c0,c1)=row g, (c2,c3)=row g+8, cols nt*8+tig*2..+1
    const int grp = lane >> 2;
    const int tig = lane & 3;
    const int rs  = wid * 16 + grp;
#pragma unroll
    for (int nt = 0; nt < 16; nt++) {
        int col = nt * 8 + tig * 2;
        float bx = s_bias[col], by = s_bias[col + 1];
        float2 v0 = make_float2(acc[nt][0] + bx, acc[nt][1] + by);
        float2 v1 = make_float2(acc[nt][2] + bx, acc[nt][3] + by);
        if (RELU) {
            v0.x = fmaxf(v0.x, 0.f); v0.y = fmaxf(v0.y, 0.f);
            v1.x = fmaxf(v1.x, 0.f); v1.y = fmaxf(v1.y, 0.f);
        }
        *reinterpret_cast<float2*>(&stage[rs * 132 + col])       = v0;
        *reinterpret_cast<float2*>(&stage[(rs + 8) * 132 + col]) = v1;
    }
    __syncthreads();

    // Coalesced store to global.
    for (int i = tid; i < 4096; i += 256) {
        int r = i >> 5, c = i & 31;
        if (row0 + r < Nrows) {
            float4 v = *reinterpret_cast<const float4*>(&stage[r * 132 + c * 4]);
            reinterpret_cast<float4*>(Y)[(size_t)(row0 + r) * 32 + c] = v;
        }
    }
}

// ---------------------------------------------------------------------------
// CSR build: degree count -> block scan -> fill
// ---------------------------------------------------------------------------
__global__ void count_deg(const int* __restrict__ ei, int* __restrict__ deg)
{
    int e = blockIdx.x * blockDim.x + threadIdx.x;
    if (e < NE) atomicAdd(&deg[ei[e]], 1);
}

#define SCAN_B 512
__global__ void scan1(const int* __restrict__ deg, int* __restrict__ rowptr,
                      int* __restrict__ bsums)
{
    __shared__ int sh[SCAN_B];
    int tid = threadIdx.x;
    int i = blockIdx.x * SCAN_B + tid;
    int v = (i < NN) ? deg[i] : 0;
    sh[tid] = v;
    __syncthreads();
#pragma unroll
    for (int off = 1; off < SCAN_B; off <<= 1) {
        int t = (tid >= off) ? sh[tid - off] : 0;
        __syncthreads();
        sh[tid] += t;
        __syncthreads();
    }
    if (i < NN) rowptr[i] = sh[tid] - v;
    if (tid == SCAN_B - 1) bsums[blockIdx.x] = sh[tid];
}

__global__ void scan2(int* __restrict__ bsums, int nb)
{
    __shared__ int sh[256];
    int tid = threadIdx.x;
    int v = (tid < nb) ? bsums[tid] : 0;
    sh[tid] = v;
    __syncthreads();
#pragma unroll
    for (int off = 1; off < 256; off <<= 1) {
        int t = (tid >= off) ? sh[tid - off] : 0;
        __syncthreads();
        sh[tid] += t;
        __syncthreads();
    }
    if (tid < nb) bsums[tid] = sh[tid] - v;
}

__global__ void scan3(int* __restrict__ rowptr, const int* __restrict__ bsums,
                      int* __restrict__ cursor)
{
    int i = blockIdx.x * SCAN_B + threadIdx.x;
    if (i < NN) {
        int r = rowptr[i] + bsums[blockIdx.x];
        rowptr[i] = r;
        cursor[i] = r;
    }
    if (i == 0) rowptr[NN] = NE;
}

__global__ void fill_csr(const int* __restrict__ ei, const float* __restrict__ mask,
                         int* __restrict__ cursor, int* __restrict__ csr_src,
                         float* __restrict__ csr_mask)
{
    int e = blockIdx.x * blockDim.x + threadIdx.x;
    if (e >= NE) return;
    int dst = ei[e];
    int src = ei[NE + e];
    int p = atomicAdd(&cursor[dst], 1);
    csr_src[p]  = src;
    csr_mask[p] = mask[e];
}

// ---------------------------------------------------------------------------
// pooled[n] = sum_{e in CSR(n)} mask_e * h[src_e] + (1+eps[l]) * h[n]
// ---------------------------------------------------------------------------
__global__ void aggregate(const float* __restrict__ h, const int* __restrict__ rowptr,
                          const int* __restrict__ csr_src, const float* __restrict__ csr_mask,
                          const float* __restrict__ eps, int l, float* __restrict__ pooled)
{
    int g = (blockIdx.x * blockDim.x + threadIdx.x) >> 5;
    int lane = threadIdx.x & 31;
    if (g >= NN) return;
    int beg = rowptr[g];
    int end = rowptr[g + 1];
    const float4* h4 = reinterpret_cast<const float4*>(h);

    float4 acc = make_float4(0.f, 0.f, 0.f, 0.f);
    int j = beg;
    for (; j + 1 < end; j += 2) {
        int   s0 = csr_src[j],   s1 = csr_src[j + 1];
        float m0 = csr_mask[j],  m1 = csr_mask[j + 1];
        float4 v0 = h4[(size_t)s0 * 32 + lane];
        float4 v1 = h4[(size_t)s1 * 32 + lane];
        acc.x += m0 * v0.x + m1 * v1.x;
        acc.y += m0 * v0.y + m1 * v1.y;
        acc.z += m0 * v0.z + m1 * v1.z;
        acc.w += m0 * v0.w + m1 * v1.w;
    }
    if (j < end) {
        int s0 = csr_src[j];
        float m0 = csr_mask[j];
        float4 v0 = h4[(size_t)s0 * 32 + lane];
        acc.x += m0 * v0.x; acc.y += m0 * v0.y;
        acc.z += m0 * v0.z; acc.w += m0 * v0.w;
    }
    float s = 1.f + eps[l];
    float4 hv = h4[(size_t)g * 32 + lane];
    acc.x += s * hv.x; acc.y += s * hv.y;
    acc.z += s * hv.z; acc.w += s * hv.w;
    reinterpret_cast<float4*>(pooled)[(size_t)g * 32 + lane] = acc;
}

// pooled_sum[g] += sum over 5 embeds of nodes in graph g (batch is sorted)
__global__ void pool_batch(const float* __restrict__ embs, const int* __restrict__ batch,
                           float* __restrict__ ps)
{
    const int j = threadIdx.x;
    const int start = blockIdx.x * 128;
    int end = start + 128;
    if (end > NN) end = NN;
    if (start >= NN) return;

    const size_t EMB = (size_t)NN * DH;
    int gc = batch[start];
    float acc = 0.f;
    for (int i = start; i < end; i++) {
        int g = batch[i];
        if (g != gc) {
            atomicAdd(&ps[(size_t)gc * 128 + j], acc);
            acc = 0.f;
            gc = g;
        }
        size_t off = (size_t)i * 128 + j;
        float s = embs[off] + embs[EMB + off] + embs[2 * EMB + off]
                + embs[3 * EMB + off] + embs[4 * EMB + off];
        acc += s;
    }
    atomicAdd(&ps[(size_t)gc * 128 + j], acc);
}

// Head: lin1 = relu(ps @ W1^T + b1); lin1d = lin1; lin2 = lin1 @ W2^T + b2; softmax
__global__ void head(const float* __restrict__ ps,
                     const float* __restrict__ W1, const float* __restrict__ b1,
                     const float* __restrict__ W2, const float* __restrict__ b2,
                     float* __restrict__ lin1, float* __restrict__ lin1d,
                     float* __restrict__ lin2, float* __restrict__ soft)
{
    __shared__ float row[128];
    __shared__ float l1s[128];
    __shared__ float l2s[8];
    const int g = blockIdx.x;
    const int j = threadIdx.x;

    row[j] = ps[(size_t)g * 128 + j];
    __syncthreads();

    float a = b1[j];
#pragma unroll 8
    for (int k = 0; k < 128; k++) a += row[k] * W1[j * 128 + k];
    a = fmaxf(a, 0.f);
    l1s[j] = a;
    lin1[(size_t)g * 128 + j] = a;
    lin1d[(size_t)g * 128 + j] = a;
    __syncthreads();

    if (j < 8) {
        float s = b2[j];
#pragma unroll 8
        for (int k = 0; k < 128; k++) s += l1s[k] * W2[j * 128 + k];
        lin2[(size_t)g * 8 + j] = s;
        l2s[j] = s;
    }
    __syncthreads();
    if (j == 0) {
        float mx = l2s[0];
#pragma unroll
        for (int q = 1; q < 8; q++) mx = fmaxf(mx, l2s[q]);
        float ex[8]; float sum = 0.f;
#pragma unroll
        for (int q = 0; q < 8; q++) { ex[q] = expf(l2s[q] - mx); sum += ex[q]; }
        float inv = 1.f / sum;
#pragma unroll
        for (int q = 0; q < 8; q++) soft[(size_t)g * 8 + q] = ex[q] * inv;
    }
}

extern "C" void kernel_launch(void* const* d_in, const int* in_sizes, int n_in,
                              void* d_out, int out_size)
{
    const float* x     = (const float*)d_in[0];
    const int*   ei    = (const int*)  d_in[1];
    const float* mask  = (const float*)d_in[2];
    const int*   batch = (const int*)  d_in[3];
    const float* eps   = (const float*)d_in[4];
    const float* Wf    = (const float*)d_in[5];
    const float* bf    = (const float*)d_in[6];
    const float* gW    = (const float*)d_in[7];   // [4][2][128][128]
    const float* gb    = (const float*)d_in[8];   // [4][2][128]
    const float* W1    = (const float*)d_in[9];
    const float* b1    = (const float*)d_in[10];
    const float* W2    = (const float*)d_in[11];
    const float* b2    = (const float*)d_in[12];

    float* out  = (float*)d_out;
    const size_t EMB = (size_t)NN * DH;
    float* embs = out;                       // [5][NN][128]
    float* ps   = out + 5 * EMB;             // [256][128]
    float* l1   = ps + (size_t)NG * DH;
    float* l1d  = l1 + (size_t)NG * DH;
    float* l2   = l1d + (size_t)NG * DH;
    float* sm   = l2 + (size_t)NG * DOUT;

    float *pooled = nullptr, *tmp = nullptr, *csr_mask = nullptr;
    int *deg = nullptr, *rowptr = nullptr, *cursor = nullptr, *bsums = nullptr, *csr_src = nullptr;
    unsigned char* wimg = nullptr;
    cudaGetSymbolAddress((void**)&pooled,   g_pooled);
    cudaGetSymbolAddress((void**)&tmp,      g_tmp);
    cudaGetSymbolAddress((void**)&deg,      g_deg);
    cudaGetSymbolAddress((void**)&rowptr,   g_rowptr);
    cudaGetSymbolAddress((void**)&cursor,   g_cursor);
    cudaGetSymbolAddress((void**)&bsums,    g_bsums);
    cudaGetSymbolAddress((void**)&csr_src,  g_csr_src);
    cudaGetSymbolAddress((void**)&csr_mask, g_csr_mask);
    cudaGetSymbolAddress((void**)&wimg,     g_wimg);

    const int GEMM_SMEM = 139264;   // Ah+Al+Bh+Bl
    cudaFuncSetAttribute(gemm_tc<false>, cudaFuncAttributeMaxDynamicSharedMemorySize, GEMM_SMEM);
    cudaFuncSetAttribute(gemm_tc<true>,  cudaFuncAttributeMaxDynamicSharedMemorySize, GEMM_SMEM);

    const int GEMM_BLOCKS = (NN + 127) / 128;            // 782
    const int SCAN_BLOCKS = (NN + SCAN_B - 1) / SCAN_B;  // 196
    const int EDGE_BLOCKS = (NE + 255) / 256;
    const int AGG_BLOCKS  = (NN * 32 + 255) / 256;
    const int POOL_BLOCKS = (NN + 127) / 128;

    // zero pooled_sum region (d_out is poisoned) + degree histogram
    cudaMemsetAsync(ps, 0, (size_t)NG * DH * sizeof(float), 0);
    cudaMemsetAsync(deg, 0, (size_t)NN * sizeof(int), 0);

    // Weight split prep (tiny) + CSR build (reused across layers)
    prep_weights<<<9, 256>>>(Wf, gW, wimg);
    count_deg<<<EDGE_BLOCKS, 256>>>(ei, deg);
    scan1<<<SCAN_BLOCKS, SCAN_B>>>(deg, rowptr, bsums);
    scan2<<<1, 256>>>(bsums, SCAN_BLOCKS);
    scan3<<<SCAN_BLOCKS, SCAN_B>>>(rowptr, bsums, cursor);
    fill_csr<<<EDGE_BLOCKS, 256>>>(ei, mask, cursor, csr_src, csr_mask);

    // first linear (NO relu): weight image 0
    gemm_tc<false><<<GEMM_BLOCKS, 256, GEMM_SMEM>>>(x, wimg, bf, embs, NN);

    for (int l = 0; l < NLAYERS; l++) {
        const float* h = embs + (size_t)l * EMB;
        aggregate<<<AGG_BLOCKS, 256>>>(h, rowptr, csr_src, csr_mask, eps, l, pooled);
        gemm_tc<true><<<GEMM_BLOCKS, 256, GEMM_SMEM>>>(
            pooled, wimg + (size_t)(1 + l * 2 + 0) * W_STRIDE, gb + (size_t)(l * 2 + 0) * 128,
            tmp, NN);
        gemm_tc<true><<<GEMM_BLOCKS, 256, GEMM_SMEM>>>(
            tmp, wimg + (size_t)(1 + l * 2 + 1) * W_STRIDE, gb + (size_t)(l * 2 + 1) * 128,
            embs + (size_t)(l + 1) * EMB, NN);
    }

    pool_batch<<<POOL_BLOCKS, 128>>>(embs, batch, ps);
    head<<<NG, 128>>>(ps, W1, b1, W2, b2, l1, l1d, l2, sm);
}

// round 15
// speedup vs baseline: 1.2553x; 1.1065x over previous
#include <cuda_runtime.h>
#include <cuda_bf16.h>
#include <math.h>

#define NN 100000
#define NE 1600000
#define NG 256
#define DH 128
#define DOUT 8
#define NLAYERS 4

// Scratch (no allocation allowed) — static device globals.
__device__ int   g_deg[NN];
__device__ int   g_rowptr[NN + 1];
__device__ int   g_cursor[NN];
__device__ int   g_bsums[256];
__device__ int   g_csr_src[NE];
__device__ float g_csr_mask[NE];
// bf16 hi/lo split operands (pre-split inputs for tensor-core GEMMs)
__device__ __align__(16) __nv_bfloat16 g_xh[(size_t)NN * DH];
__device__ __align__(16) __nv_bfloat16 g_xl[(size_t)NN * DH];
__device__ __align__(16) __nv_bfloat16 g_ph[(size_t)NN * DH];
__device__ __align__(16) __nv_bfloat16 g_pl[(size_t)NN * DH];
__device__ __align__(16) __nv_bfloat16 g_th[(size_t)NN * DH];
__device__ __align__(16) __nv_bfloat16 g_tl[(size_t)NN * DH];

// Weight images: per weight 69632 B = hi[128 rows x 272B] + lo[same]
#define W_PITCH   272              // 136 bf16 per row (16B*17 -> ldmatrix conflict-free)
#define W_HALF    34816            // 128 * 272
#define W_STRIDE  69632
__device__ __align__(16) unsigned char g_wimg[9 * W_STRIDE];

// ===========================================================================
// helpers
// ===========================================================================
__device__ __forceinline__ unsigned smem_u32(const void* p) {
    unsigned a;
    asm("{ .reg .u64 t; cvta.to.shared.u64 t, %1; cvt.u32.u64 %0, t; }"
        : "=r"(a) : "l"(p));
    return a;
}

#define LDSM4(d, addr) \
    asm volatile("ldmatrix.sync.aligned.m8n8.x4.shared.b16 {%0,%1,%2,%3}, [%4];" \
        : "=r"((d)[0]), "=r"((d)[1]), "=r"((d)[2]), "=r"((d)[3]) : "r"(addr))

#define MMA16816(c, a, b0, b1) \
    asm volatile("mma.sync.aligned.m16n8k16.row.col.f32.bf16.bf16.f32 " \
        "{%0,%1,%2,%3}, {%4,%5,%6,%7}, {%8,%9}, {%0,%1,%2,%3};" \
        : "+f"((c)[0]), "+f"((c)[1]), "+f"((c)[2]), "+f"((c)[3]) \
        : "r"((a)[0]), "r"((a)[1]), "r"((a)[2]), "r"((a)[3]), "r"(b0), "r"(b1))

// Convert 8 fp32 -> packed bf16 hi (uint4) and bf16 lo (uint4)
__device__ __forceinline__ void cvt8(const float* f, uint4& hv, uint4& lv) {
    __nv_bfloat162 hp[4], lp[4];
#pragma unroll
    for (int i = 0; i < 4; i++) {
        __nv_bfloat16 h0 = __float2bfloat16_rn(f[2 * i]);
        __nv_bfloat16 h1 = __float2bfloat16_rn(f[2 * i + 1]);
        float l0 = f[2 * i]     - __bfloat162float(h0);
        float l1 = f[2 * i + 1] - __bfloat162float(h1);
        hp[i].x = h0; hp[i].y = h1;
        lp[i].x = __float2bfloat16_rn(l0);
        lp[i].y = __float2bfloat16_rn(l1);
    }
    hv.x = *reinterpret_cast<unsigned*>(&hp[0]);
    hv.y = *reinterpret_cast<unsigned*>(&hp[1]);
    hv.z = *reinterpret_cast<unsigned*>(&hp[2]);
    hv.w = *reinterpret_cast<unsigned*>(&hp[3]);
    lv.x = *reinterpret_cast<unsigned*>(&lp[0]);
    lv.y = *reinterpret_cast<unsigned*>(&lp[1]);
    lv.z = *reinterpret_cast<unsigned*>(&lp[2]);
    lv.w = *reinterpret_cast<unsigned*>(&lp[3]);
}

// ---------------------------------------------------------------------------
// Weight prep: split 9 W matrices into bf16 hi/lo padded-row images.
// ---------------------------------------------------------------------------
__global__ void prep_weights(const float* __restrict__ Wf, const float* __restrict__ gW,
                             unsigned char* __restrict__ wimg)
{
    int b = blockIdx.x;
    const float* W = (b == 0) ? Wf : (gW + (size_t)(b - 1) * 128 * 128);
    unsigned char* hi = wimg + (size_t)b * W_STRIDE;
    unsigned char* lo = hi + W_HALF;
    for (int g = threadIdx.x; g < 2048; g += blockDim.x) {
        int r  = g >> 4;
        int k0 = (g & 15) << 3;
        float f[8];
#pragma unroll
        for (int q = 0; q < 8; q++) f[q] = W[r * 128 + k0 + q];
        uint4 hv, lv;
        cvt8(f, hv, lv);
        unsigned off = (unsigned)r * W_PITCH + (unsigned)k0 * 2;
        *reinterpret_cast<uint4*>(hi + off) = hv;
        *reinterpret_cast<uint4*>(lo + off) = lv;
    }
}

// Split x (fp32) into bf16 hi/lo global arrays — once per launch.
__global__ void split_x(const float* __restrict__ x,
                        __nv_bfloat16* __restrict__ xh, __nv_bfloat16* __restrict__ xl)
{
    size_t i = (size_t)blockIdx.x * blockDim.x + threadIdx.x;   // over NN*128/8
    float4 v0 = reinterpret_cast<const float4*>(x)[2 * i];
    float4 v1 = reinterpret_cast<const float4*>(x)[2 * i + 1];
    float f[8] = { v0.x, v0.y, v0.z, v0.w, v1.x, v1.y, v1.z, v1.w };
    uint4 hv, lv;
    cvt8(f, hv, lv);
    reinterpret_cast<uint4*>(xh)[i] = hv;
    reinterpret_cast<uint4*>(xl)[i] = lv;
}

// ---------------------------------------------------------------------------
// Tensor-core GEMM via mma.sync (bf16x3 emulated fp32):
//   Y[N,128] = act(X[N,128] @ W^T + b),  X given pre-split as (Xh, Xl) bf16.
// CTA: 64-row tile, 256 threads (8 warps), 2 CTAs/SM.
// Warp (wid&3) -> rows (wid&3)*16..+15 ; (wid>>2) -> col half *64.
// Dyn smem 104448 B: Ah[0,17408) Al[17408,34816) Bh[34816,69632) Bl[69632,104448)
// OUT_PAIR: write Y as bf16 hi/lo pair (for next GEMM); else fp32.
// ---------------------------------------------------------------------------
template<bool RELU, bool OUT_PAIR>
__global__ void __launch_bounds__(256, 2)
gemm64(const __nv_bfloat16* __restrict__ Xh, const __nv_bfloat16* __restrict__ Xl,
       const unsigned char* __restrict__ wimg_tile, const float* __restrict__ bias,
       float* __restrict__ Yf, __nv_bfloat16* __restrict__ Yh,
       __nv_bfloat16* __restrict__ Yl, int Nrows)
{
    extern __shared__ char sm[];
    char* Ah = sm;
    char* Al = sm + 17408;
    char* Bh = sm + 34816;
    float* stage = reinterpret_cast<float*>(sm);   // 64 x 132 fp32 (post-MMA)

    __shared__ float s_bias[128];

    const int tid  = threadIdx.x;
    const int wid  = tid >> 5;
    const int lane = tid & 31;
    const int row0 = blockIdx.x * 64;

    if (tid < 128) s_bias[tid] = bias[tid];

    // Copy weight hi/lo images (68KB linear, coalesced)
    {
        const uint4* wsrc = reinterpret_cast<const uint4*>(wimg_tile);
        uint4* bdst = reinterpret_cast<uint4*>(Bh);
        for (int i = tid; i < 4352; i += 256) bdst[i] = wsrc[i];
    }
    // Copy pre-split A tile (pure copy, no cvt)
    for (int i = tid; i < 1024; i += 256) {
        int r = i >> 4, c = i & 15;
        int row = row0 + r;
        uint4 hv = make_uint4(0, 0, 0, 0), lv = make_uint4(0, 0, 0, 0);
        if (row < Nrows) {
            hv = reinterpret_cast<const uint4*>(Xh)[(size_t)row * 16 + c];
            lv = reinterpret_cast<const uint4*>(Xl)[(size_t)row * 16 + c];
        }
        *reinterpret_cast<uint4*>(Ah + r * W_PITCH + c * 16) = hv;
        *reinterpret_cast<uint4*>(Al + r * W_PITCH + c * 16) = lv;
    }
    __syncthreads();

    const int wr = (wid & 3) * 16;     // warp row base
    const int wc = (wid >> 2) * 64;    // warp col base (= W row base)

    unsigned aBaseH = smem_u32(Ah)
                    + (unsigned)(wr + (lane & 15)) * W_PITCH
                    + (unsigned)(((lane >> 4) & 1) * 16);
    unsigned aBaseL = aBaseH + 17408;
    unsigned bRowOff = (unsigned)((((lane >> 4) & 1) * 8 + (lane & 7)) * W_PITCH
                                  + ((lane >> 3) & 1) * 16);
    unsigned bBaseH = smem_u32(Bh) + (unsigned)wc * W_PITCH + bRowOff;
    unsigned bBaseL = bBaseH + 34816;

    float acc[8][4];
#pragma unroll
    for (int n = 0; n < 8; n++)
#pragma unroll
        for (int q = 0; q < 4; q++) acc[n][q] = 0.f;

#pragma unroll
    for (int ks = 0; ks < 8; ks++) {
        unsigned ah[4], al[4];
        LDSM4(ah, aBaseH + ks * 32);
        LDSM4(al, aBaseL + ks * 32);
#pragma unroll
        for (int np = 0; np < 4; np++) {           // n-tile pair (2np, 2np+1)
            unsigned bh[4], bl[4];
            unsigned boff = (unsigned)(np * 16 * W_PITCH + ks * 32);
            LDSM4(bh, bBaseH + boff);
            LDSM4(bl, bBaseL + boff);
            MMA16816(acc[2 * np],     ah, bh[0], bh[1]);
            MMA16816(acc[2 * np],     ah, bl[0], bl[1]);
            MMA16816(acc[2 * np],     al, bh[0], bh[1]);
            MMA16816(acc[2 * np + 1], ah, bh[2], bh[3]);
            MMA16816(acc[2 * np + 1], ah, bl[2], bl[3]);
            MMA16816(acc[2 * np + 1], al, bh[2], bh[3]);
        }
    }
    __syncthreads();   // done reading A/B smem; reuse as stage

    // Epilogue: C frag (c0,c1)=row grp, (c2,c3)=row grp+8, cols wc+nt*8+tig*2
    const int grp = lane >> 2;
    const int tig = lane & 3;
    const int rs  = wr + grp;
#pragma unroll
    for (int nt = 0; nt < 8; nt++) {
        int col = wc + nt * 8 + tig * 2;
        float bx = s_bias[col], by = s_bias[col + 1];
        float2 v0 = make_float2(acc[nt][0] + bx, acc[nt][1] + by);
        float2 v1 = make_float2(acc[nt][2] + bx, acc[nt][3] + by);
        if (RELU) {
            v0.x = fmaxf(v0.x, 0.f); v0.y = fmaxf(v0.y, 0.f);
            v1.x = fmaxf(v1.x, 0.f); v1.y = fmaxf(v1.y, 0.f);
        }
        *reinterpret_cast<float2*>(&stage[rs * 132 + col])       = v0;
        *reinterpret_cast<float2*>(&stage[(rs + 8) * 132 + col]) = v1;
    }
    __syncthreads();

    if (OUT_PAIR) {
        // Split to bf16 hi/lo and store (coalesced 16B per thread per array)
        for (int i = tid; i < 1024; i += 256) {
            int r = i >> 4, c = i & 15;
            if (row0 + r < Nrows) {
                float f[8];
                float4 s0 = *reinterpret_cast<const float4*>(&stage[r * 132 + c * 8]);
                float4 s1 = *reinterpret_cast<const float4*>(&stage[r * 132 + c * 8 + 4]);
                f[0] = s0.x; f[1] = s0.y; f[2] = s0.z; f[3] = s0.w;
                f[4] = s1.x; f[5] = s1.y; f[6] = s1.z; f[7] = s1.w;
                uint4 hv, lv;
                cvt8(f, hv, lv);
                reinterpret_cast<uint4*>(Yh)[(size_t)(row0 + r) * 16 + c] = hv;
                reinterpret_cast<uint4*>(Yl)[(size_t)(row0 + r) * 16 + c] = lv;
            }
        }
    } else {
        for (int i = tid; i < 2048; i += 256) {
            int r = i >> 5, c = i & 31;
            if (row0 + r < Nrows) {
                float4 v = *reinterpret_cast<const float4*>(&stage[r * 132 + c * 4]);
                reinterpret_cast<float4*>(Yf)[(size_t)(row0 + r) * 32 + c] = v;
            }
        }
    }
}

// ---------------------------------------------------------------------------
// CSR build: degree count -> block scan -> fill
// ---------------------------------------------------------------------------
__global__ void count_deg(const int* __restrict__ ei, int* __restrict__ deg)
{
    int e = blockIdx.x * blockDim.x + threadIdx.x;
    if (e < NE) atomicAdd(&deg[ei[e]], 1);
}

#define SCAN_B 512
__global__ void scan1(const int* __restrict__ deg, int* __restrict__ rowptr,
                      int* __restrict__ bsums)
{
    __shared__ int sh[SCAN_B];
    int tid = threadIdx.x;
    int i = blockIdx.x * SCAN_B + tid;
    int v = (i < NN) ? deg[i] : 0;
    sh[tid] = v;
    __syncthreads();
#pragma unroll
    for (int off = 1; off < SCAN_B; off <<= 1) {
        int t = (tid >= off) ? sh[tid - off] : 0;
        __syncthreads();
        sh[tid] += t;
        __syncthreads();
    }
    if (i < NN) rowptr[i] = sh[tid] - v;
    if (tid == SCAN_B - 1) bsums[blockIdx.x] = sh[tid];
}

__global__ void scan2(int* __restrict__ bsums, int nb)
{
    __shared__ int sh[256];
    int tid = threadIdx.x;
    int v = (tid < nb) ? bsums[tid] : 0;
    sh[tid] = v;
    __syncthreads();
#pragma unroll
    for (int off = 1; off < 256; off <<= 1) {
        int t = (tid >= off) ? sh[tid - off] : 0;
        __syncthreads();
        sh[tid] += t;
        __syncthreads();
    }
    if (tid < nb) bsums[tid] = sh[tid] - v;
}

__global__ void scan3(int* __restrict__ rowptr, const int* __restrict__ bsums,
                      int* __restrict__ cursor)
{
    int i = blockIdx.x * SCAN_B + threadIdx.x;
    if (i < NN) {
        int r = rowptr[i] + bsums[blockIdx.x];
        rowptr[i] = r;
        cursor[i] = r;
    }
    if (i == 0) rowptr[NN] = NE;
}

__global__ void fill_csr(const int* __restrict__ ei, const float* __restrict__ mask,
                         int* __restrict__ cursor, int* __restrict__ csr_src,
                         float* __restrict__ csr_mask)
{
    int e = blockIdx.x * blockDim.x + threadIdx.x;
    if (e >= NE) return;
    int dst = ei[e];
    int src = ei[NE + e];
    int p = atomicAdd(&cursor[dst], 1);
    csr_src[p]  = src;
    csr_mask[p] = mask[e];
}

// ---------------------------------------------------------------------------
// pooled[n] = sum_{e in CSR(n)} mask_e * h[src_e] + (1+eps[l]) * h[n]
// Output written directly as bf16 hi/lo split (feeds the next GEMM).
// ---------------------------------------------------------------------------
__global__ void aggregate(const float* __restrict__ h, const int* __restrict__ rowptr,
                          const int* __restrict__ csr_src, const float* __restrict__ csr_mask,
                          const float* __restrict__ eps, int l,
                          __nv_bfloat16* __restrict__ ph, __nv_bfloat16* __restrict__ pl)
{
    int g = (blockIdx.x * blockDim.x + threadIdx.x) >> 5;
    int lane = threadIdx.x & 31;
    if (g >= NN) return;
    int beg = rowptr[g];
    int end = rowptr[g + 1];
    const float4* h4 = reinterpret_cast<const float4*>(h);

    float4 acc = make_float4(0.f, 0.f, 0.f, 0.f);
    int j = beg;
    for (; j + 1 < end; j += 2) {
        int   s0 = csr_src[j],   s1 = csr_src[j + 1];
        float m0 = csr_mask[j],  m1 = csr_mask[j + 1];
        float4 v0 = h4[(size_t)s0 * 32 + lane];
        float4 v1 = h4[(size_t)s1 * 32 + lane];
        acc.x += m0 * v0.x + m1 * v1.x;
        acc.y += m0 * v0.y + m1 * v1.y;
        acc.z += m0 * v0.z + m1 * v1.z;
        acc.w += m0 * v0.w + m1 * v1.w;
    }
    if (j < end) {
        int s0 = csr_src[j];
        float m0 = csr_mask[j];
        float4 v0 = h4[(size_t)s0 * 32 + lane];
        acc.x += m0 * v0.x; acc.y += m0 * v0.y;
        acc.z += m0 * v0.z; acc.w += m0 * v0.w;
    }
    float s = 1.f + eps[l];
    float4 hv4 = h4[(size_t)g * 32 + lane];
    acc.x += s * hv4.x; acc.y += s * hv4.y;
    acc.z += s * hv4.z; acc.w += s * hv4.w;

    // split to bf16 hi/lo, 4 values -> one uint2 per array
    __nv_bfloat162 hp0, hp1, lp0, lp1;
    hp0.x = __float2bfloat16_rn(acc.x);
    hp0.y = __float2bfloat16_rn(acc.y);
    hp1.x = __float2bfloat16_rn(acc.z);
    hp1.y = __float2bfloat16_rn(acc.w);
    lp0.x = __float2bfloat16_rn(acc.x - __bfloat162float(hp0.x));
    lp0.y = __float2bfloat16_rn(acc.y - __bfloat162float(hp0.y));
    lp1.x = __float2bfloat16_rn(acc.z - __bfloat162float(hp1.x));
    lp1.y = __float2bfloat16_rn(acc.w - __bfloat162float(hp1.y));
    uint2 hw, lw;
    hw.x = *reinterpret_cast<unsigned*>(&hp0);
    hw.y = *reinterpret_cast<unsigned*>(&hp1);
    lw.x = *reinterpret_cast<unsigned*>(&lp0);
    lw.y = *reinterpret_cast<unsigned*>(&lp1);
    reinterpret_cast<uint2*>(ph)[(size_t)g * 32 + lane] = hw;
    reinterpret_cast<uint2*>(pl)[(size_t)g * 32 + lane] = lw;
}

// pooled_sum[g] += sum over 5 embeds of nodes in graph g (batch is sorted)
__global__ void pool_batch(const float* __restrict__ embs, const int* __restrict__ batch,
                           float* __restrict__ ps)
{
    const int j = threadIdx.x;
    const int start = blockIdx.x * 128;
    int end = start + 128;
    if (end > NN) end = NN;
    if (start >= NN) return;

    const size_t EMB = (size_t)NN * DH;
    int gc = batch[start];
    float acc = 0.f;
    for (int i = start; i < end; i++) {
        int g = batch[i];
        if (g != gc) {
            atomicAdd(&ps[(size_t)gc * 128 + j], acc);
            acc = 0.f;
            gc = g;
        }
        size_t off = (size_t)i * 128 + j;
        float s = embs[off] + embs[EMB + off] + embs[2 * EMB + off]
                + embs[3 * EMB + off] + embs[4 * EMB + off];
        acc += s;
    }
    atomicAdd(&ps[(size_t)gc * 128 + j], acc);
}

// Head: lin1 = relu(ps @ W1^T + b1); lin1d = lin1; lin2 = lin1 @ W2^T + b2; softmax
__global__ void head(const float* __restrict__ ps,
                     const float* __restrict__ W1, const float* __restrict__ b1,
                     const float* __restrict__ W2, const float* __restrict__ b2,
                     float* __restrict__ lin1, float* __restrict__ lin1d,
                     float* __restrict__ lin2, float* __restrict__ soft)
{
    __shared__ float row[128];
    __shared__ float l1s[128];
    __shared__ float l2s[8];
    const int g = blockIdx.x;
    const int j = threadIdx.x;

    row[j] = ps[(size_t)g * 128 + j];
    __syncthreads();

    float a = b1[j];
#pragma unroll 8
    for (int k = 0; k < 128; k++) a += row[k] * W1[j * 128 + k];
    a = fmaxf(a, 0.f);
    l1s[j] = a;
    lin1[(size_t)g * 128 + j] = a;
    lin1d[(size_t)g * 128 + j] = a;
    __syncthreads();

    if (j < 8) {
        float s = b2[j];
#pragma unroll 8
        for (int k = 0; k < 128; k++) s += l1s[k] * W2[j * 128 + k];
        lin2[(size_t)g * 8 + j] = s;
        l2s[j] = s;
    }
    __syncthreads();
    if (j == 0) {
        float mx = l2s[0];
#pragma unroll
        for (int q = 1; q < 8; q++) mx = fmaxf(mx, l2s[q]);
        float ex[8]; float sum = 0.f;
#pragma unroll
        for (int q = 0; q < 8; q++) { ex[q] = expf(l2s[q] - mx); sum += ex[q]; }
        float inv = 1.f / sum;
#pragma unroll
        for (int q = 0; q < 8; q++) soft[(size_t)g * 8 + q] = ex[q] * inv;
    }
}

extern "C" void kernel_launch(void* const* d_in, const int* in_sizes, int n_in,
                              void* d_out, int out_size)
{
    const float* x     = (const float*)d_in[0];
    const int*   ei    = (const int*)  d_in[1];
    const float* mask  = (const float*)d_in[2];
    const int*   batch = (const int*)  d_in[3];
    const float* eps   = (const float*)d_in[4];
    const float* Wf    = (const float*)d_in[5];
    const float* bf    = (const float*)d_in[6];
    const float* gW    = (const float*)d_in[7];   // [4][2][128][128]
    const float* gb    = (const float*)d_in[8];   // [4][2][128]
    const float* W1    = (const float*)d_in[9];
    const float* b1    = (const float*)d_in[10];
    const float* W2    = (const float*)d_in[11];
    const float* b2    = (const float*)d_in[12];

    float* out  = (float*)d_out;
    const size_t EMB = (size_t)NN * DH;
    float* embs = out;                       // [5][NN][128]
    float* ps   = out + 5 * EMB;             // [256][128]
    float* l1   = ps + (size_t)NG * DH;
    float* l1d  = l1 + (size_t)NG * DH;
    float* l2   = l1d + (size_t)NG * DH;
    float* sm   = l2 + (size_t)NG * DOUT;

    float* csr_mask = nullptr;
    int *deg = nullptr, *rowptr = nullptr, *cursor = nullptr, *bsums = nullptr, *csr_src = nullptr;
    unsigned char* wimg = nullptr;
    __nv_bfloat16 *xh = nullptr, *xl = nullptr, *ph = nullptr, *pl = nullptr, *th = nullptr, *tl = nullptr;
    cudaGetSymbolAddress((void**)&deg,      g_deg);
    cudaGetSymbolAddress((void**)&rowptr,   g_rowptr);
    cudaGetSymbolAddress((void**)&cursor,   g_cursor);
    cudaGetSymbolAddress((void**)&bsums,    g_bsums);
    cudaGetSymbolAddress((void**)&csr_src,  g_csr_src);
    cudaGetSymbolAddress((void**)&csr_mask, g_csr_mask);
    cudaGetSymbolAddress((void**)&wimg,     g_wimg);
    cudaGetSymbolAddress((void**)&xh,       g_xh);
    cudaGetSymbolAddress((void**)&xl,       g_xl);
    cudaGetSymbolAddress((void**)&ph,       g_ph);
    cudaGetSymbolAddress((void**)&pl,       g_pl);
    cudaGetSymbolAddress((void**)&th,       g_th);
    cudaGetSymbolAddress((void**)&tl,       g_tl);

    const int GEMM_SMEM = 104448;   // Ah+Al+Bh+Bl (64-row tile)
    cudaFuncSetAttribute((const void*)gemm64<false, false>,
                         cudaFuncAttributeMaxDynamicSharedMemorySize, GEMM_SMEM);
    cudaFuncSetAttribute((const void*)gemm64<true, true>,
                         cudaFuncAttributeMaxDynamicSharedMemorySize, GEMM_SMEM);
    cudaFuncSetAttribute((const void*)gemm64<true, false>,
                         cudaFuncAttributeMaxDynamicSharedMemorySize, GEMM_SMEM);

    const int GEMM_BLOCKS = (NN + 63) / 64;              // 1563
    const int SCAN_BLOCKS = (NN + SCAN_B - 1) / SCAN_B;  // 196
    const int EDGE_BLOCKS = (NE + 255) / 256;
    const int AGG_BLOCKS  = (NN * 32 + 255) / 256;
    const int POOL_BLOCKS = (NN + 127) / 128;
    const int SPLIT_BLOCKS = (NN * DH / 8 + 255) / 256;  // 6250

    // zero pooled_sum region (d_out is poisoned) + degree histogram
    cudaMemsetAsync(ps, 0, (size_t)NG * DH * sizeof(float), 0);
    cudaMemsetAsync(deg, 0, (size_t)NN * sizeof(int), 0);

    // Prep: weight split, x split, CSR build (all reused across layers)
    prep_weights<<<9, 256>>>(Wf, gW, wimg);
    split_x<<<SPLIT_BLOCKS, 256>>>(x, xh, xl);
    count_deg<<<EDGE_BLOCKS, 256>>>(ei, deg);
    scan1<<<SCAN_BLOCKS, SCAN_B>>>(deg, rowptr, bsums);
    scan2<<<1, 256>>>(bsums, SCAN_BLOCKS);
    scan3<<<SCAN_BLOCKS, SCAN_B>>>(rowptr, bsums, cursor);
    fill_csr<<<EDGE_BLOCKS, 256>>>(ei, mask, cursor, csr_src, csr_mask);

    // first linear (NO relu) -> embs[0] fp32
    gemm64<false, false><<<GEMM_BLOCKS, 256, GEMM_SMEM>>>(
        xh, xl, wimg, bf, embs, nullptr, nullptr, NN);

    for (int l = 0; l < NLAYERS; l++) {
        const float* h = embs + (size_t)l * EMB;
        aggregate<<<AGG_BLOCKS, 256>>>(h, rowptr, csr_src, csr_mask, eps, l, ph, pl);
        // MLP layer 0: relu, output bf16 pair (tmp never needed in fp32)
        gemm64<true, true><<<GEMM_BLOCKS, 256, GEMM_SMEM>>>(
            ph, pl, wimg + (size_t)(1 + l * 2 + 0) * W_STRIDE,
            gb + (size_t)(l * 2 + 0) * 128, nullptr, th, tl, NN);
        // MLP layer 1: relu, output fp32 embs[l+1]
        gemm64<true, false><<<GEMM_BLOCKS, 256, GEMM_SMEM>>>(
            th, tl, wimg + (size_t)(1 + l * 2 + 1) * W_STRIDE,
            gb + (size_t)(l * 2 + 1) * 128,
            embs + (size_t)(l + 1) * EMB, nullptr, nullptr, NN);
    }

    pool_batch<<<POOL_BLOCKS, 128>>>(embs, batch, ps);
    head<<<NG, 128>>>(ps, W1, b1, W2, b2, l1, l1d, l2, sm);
}

// round 17
// speedup vs baseline: 1.7691x; 1.4093x over previous
#include <cuda_runtime.h>
#include <cuda_bf16.h>
#include <math.h>

#define NN 100000
#define NE 1600000
#define NG 256
#define DH 128
#define DOUT 8
#define NLAYERS 4
#define NT_TILES 1563            // ceil(NN/64)

// Scratch (no allocation allowed) — static device globals.
__device__ int   g_deg[NN];
__device__ int   g_rowptr[NN + 1];
__device__ int   g_cursor[NN];
__device__ int   g_bsums[256];
__device__ int   g_csr_src[NE];
__device__ float g_csr_mask[NE];
// bf16 hi/lo split operands (pre-split inputs for tensor-core GEMMs)
__device__ __align__(16) __nv_bfloat16 g_xh[(size_t)NN * DH];
__device__ __align__(16) __nv_bfloat16 g_xl[(size_t)NN * DH];
__device__ __align__(16) __nv_bfloat16 g_ph[(size_t)NN * DH];
__device__ __align__(16) __nv_bfloat16 g_pl[(size_t)NN * DH];

// Weight images: per weight 69632 B = hi[128 rows x 272B] + lo[same]
#define W_PITCH   272              // 136 bf16 per row (16B*17 -> ldmatrix conflict-free)
#define W_HALF    34816            // 128 * 272
#define W_STRIDE  69632
__device__ __align__(16) unsigned char g_wimg[9 * W_STRIDE];

// ===========================================================================
// helpers
// ===========================================================================
__device__ __forceinline__ unsigned smem_u32(const void* p) {
    unsigned a;
    asm("{ .reg .u64 t; cvta.to.shared.u64 t, %1; cvt.u32.u64 %0, t; }"
        : "=r"(a) : "l"(p));
    return a;
}

#define LDSM4(d, addr) \
    asm volatile("ldmatrix.sync.aligned.m8n8.x4.shared.b16 {%0,%1,%2,%3}, [%4];" \
        : "=r"((d)[0]), "=r"((d)[1]), "=r"((d)[2]), "=r"((d)[3]) : "r"(addr))

#define MMA16816(c, a, b0, b1) \
    asm volatile("mma.sync.aligned.m16n8k16.row.col.f32.bf16.bf16.f32 " \
        "{%0,%1,%2,%3}, {%4,%5,%6,%7}, {%8,%9}, {%0,%1,%2,%3};" \
        : "+f"((c)[0]), "+f"((c)[1]), "+f"((c)[2]), "+f"((c)[3]) \
        : "r"((a)[0]), "r"((a)[1]), "r"((a)[2]), "r"((a)[3]), "r"(b0), "r"(b1))

__device__ __forceinline__ void cpa16(unsigned dst, const void* src) {
    asm volatile("cp.async.cg.shared.global [%0], [%1], 16;"
                 :: "r"(dst), "l"(src));
}
__device__ __forceinline__ void cpa16p(unsigned dst, const void* src, bool pred) {
    int sz = pred ? 16 : 0;
    asm volatile("cp.async.cg.shared.global [%0], [%1], 16, %2;"
                 :: "r"(dst), "l"(src), "r"(sz));
}
#define CPA_COMMIT() asm volatile("cp.async.commit_group;" ::: "memory")
#define CPA_WAIT0()  asm volatile("cp.async.wait_group 0;" ::: "memory")

// Convert 8 fp32 -> packed bf16 hi (uint4) and bf16 lo (uint4)
__device__ __forceinline__ void cvt8(const float* f, uint4& hv, uint4& lv) {
    __nv_bfloat162 hp[4], lp[4];
#pragma unroll
    for (int i = 0; i < 4; i++) {
        __nv_bfloat16 h0 = __float2bfloat16_rn(f[2 * i]);
        __nv_bfloat16 h1 = __float2bfloat16_rn(f[2 * i + 1]);
        float l0 = f[2 * i]     - __bfloat162float(h0);
        float l1 = f[2 * i + 1] - __bfloat162float(h1);
        hp[i].x = h0; hp[i].y = h1;
        lp[i].x = __float2bfloat16_rn(l0);
        lp[i].y = __float2bfloat16_rn(l1);
    }
    hv.x = *reinterpret_cast<unsigned*>(&hp[0]);
    hv.y = *reinterpret_cast<unsigned*>(&hp[1]);
    hv.z = *reinterpret_cast<unsigned*>(&hp[2]);
    hv.w = *reinterpret_cast<unsigned*>(&hp[3]);
    lv.x = *reinterpret_cast<unsigned*>(&lp[0]);
    lv.y = *reinterpret_cast<unsigned*>(&lp[1]);
    lv.z = *reinterpret_cast<unsigned*>(&lp[2]);
    lv.w = *reinterpret_cast<unsigned*>(&lp[3]);
}

// ---------------------------------------------------------------------------
// Weight prep: split 9 W matrices into bf16 hi/lo padded-row images.
// ---------------------------------------------------------------------------
__global__ void prep_weights(const float* __restrict__ Wf, const float* __restrict__ gW,
                             unsigned char* __restrict__ wimg)
{
    int b = blockIdx.x;
    const float* W = (b == 0) ? Wf : (gW + (size_t)(b - 1) * 128 * 128);
    unsigned char* hi = wimg + (size_t)b * W_STRIDE;
    unsigned char* lo = hi + W_HALF;
    for (int g = threadIdx.x; g < 2048; g += blockDim.x) {
        int r  = g >> 4;
        int k0 = (g & 15) << 3;
        float f[8];
#pragma unroll
        for (int q = 0; q < 8; q++) f[q] = W[r * 128 + k0 + q];
        uint4 hv, lv;
        cvt8(f, hv, lv);
        unsigned off = (unsigned)r * W_PITCH + (unsigned)k0 * 2;
        *reinterpret_cast<uint4*>(hi + off) = hv;
        *reinterpret_cast<uint4*>(lo + off) = lv;
    }
}

// Split x (fp32) into bf16 hi/lo global arrays — once per launch.
__global__ void split_x(const float* __restrict__ x,
                        __nv_bfloat16* __restrict__ xh, __nv_bfloat16* __restrict__ xl)
{
    size_t i = (size_t)blockIdx.x * blockDim.x + threadIdx.x;   // over NN*128/8
    float4 v0 = reinterpret_cast<const float4*>(x)[2 * i];
    float4 v1 = reinterpret_cast<const float4*>(x)[2 * i + 1];
    float f[8] = { v0.x, v0.y, v0.z, v0.w, v1.x, v1.y, v1.z, v1.w };
    uint4 hv, lv;
    cvt8(f, hv, lv);
    reinterpret_cast<uint4*>(xh)[i] = hv;
    reinterpret_cast<uint4*>(xl)[i] = lv;
}

// ---------------------------------------------------------------------------
// First linear: Y[N,128] = X @ W^T + b (no relu), non-persistent gemm (proven).
// 64-row tile, 256 threads, 2 CTAs/SM. smem 104448 B.
// ---------------------------------------------------------------------------
__global__ void __launch_bounds__(256, 2)
gemm64(const __nv_bfloat16* __restrict__ Xh, const __nv_bfloat16* __restrict__ Xl,
       const unsigned char* __restrict__ wimg_tile, const float* __restrict__ bias,
       float* __restrict__ Yf, int Nrows)
{
    extern __shared__ char sm[];
    char* Ah = sm;
    char* Al = sm + 17408;
    char* Bh = sm + 34816;
    float* stage = reinterpret_cast<float*>(sm);

    __shared__ float s_bias[128];

    const int tid  = threadIdx.x;
    const int wid  = tid >> 5;
    const int lane = tid & 31;
    const int row0 = blockIdx.x * 64;

    if (tid < 128) s_bias[tid] = bias[tid];

    {
        const uint4* wsrc = reinterpret_cast<const uint4*>(wimg_tile);
        uint4* bdst = reinterpret_cast<uint4*>(Bh);
        for (int i = tid; i < 4352; i += 256) bdst[i] = wsrc[i];
    }
    for (int i = tid; i < 1024; i += 256) {
        int r = i >> 4, c = i & 15;
        int row = row0 + r;
        uint4 hv = make_uint4(0, 0, 0, 0), lv = make_uint4(0, 0, 0, 0);
        if (row < Nrows) {
            hv = reinterpret_cast<const uint4*>(Xh)[(size_t)row * 16 + c];
            lv = reinterpret_cast<const uint4*>(Xl)[(size_t)row * 16 + c];
        }
        *reinterpret_cast<uint4*>(Ah + r * W_PITCH + c * 16) = hv;
        *reinterpret_cast<uint4*>(Al + r * W_PITCH + c * 16) = lv;
    }
    __syncthreads();

    const int wr = (wid & 3) * 16;
    const int wc = (wid >> 2) * 64;

    unsigned aBaseH = smem_u32(Ah)
                    + (unsigned)(wr + (lane & 15)) * W_PITCH
                    + (unsigned)(((lane >> 4) & 1) * 16);
    unsigned aBaseL = aBaseH + 17408;
    unsigned bRowOff = (unsigned)((((lane >> 4) & 1) * 8 + (lane & 7)) * W_PITCH
                                  + ((lane >> 3) & 1) * 16);
    unsigned bBaseH = smem_u32(Bh) + (unsigned)wc * W_PITCH + bRowOff;
    unsigned bBaseL = bBaseH + 34816;

    float acc[8][4];
#pragma unroll
    for (int n = 0; n < 8; n++)
#pragma unroll
        for (int q = 0; q < 4; q++) acc[n][q] = 0.f;

#pragma unroll
    for (int ks = 0; ks < 8; ks++) {
        unsigned ah[4], al[4];
        LDSM4(ah, aBaseH + ks * 32);
        LDSM4(al, aBaseL + ks * 32);
#pragma unroll
        for (int np = 0; np < 4; np++) {
            unsigned bh[4], bl[4];
            unsigned boff = (unsigned)(np * 16 * W_PITCH + ks * 32);
            LDSM4(bh, bBaseH + boff);
            LDSM4(bl, bBaseL + boff);
            MMA16816(acc[2 * np],     ah, bh[0], bh[1]);
            MMA16816(acc[2 * np],     ah, bl[0], bl[1]);
            MMA16816(acc[2 * np],     al, bh[0], bh[1]);
            MMA16816(acc[2 * np + 1], ah, bh[2], bh[3]);
            MMA16816(acc[2 * np + 1], ah, bl[2], bl[3]);
            MMA16816(acc[2 * np + 1], al, bh[2], bh[3]);
        }
    }
    __syncthreads();

    const int grp = lane >> 2;
    const int tig = lane & 3;
    const int rs  = wr + grp;
#pragma unroll
    for (int nt = 0; nt < 8; nt++) {
        int col = wc + nt * 8 + tig * 2;
        float bx = s_bias[col], by = s_bias[col + 1];
        *reinterpret_cast<float2*>(&stage[rs * 132 + col]) =
            make_float2(acc[nt][0] + bx, acc[nt][1] + by);
        *reinterpret_cast<float2*>(&stage[(rs + 8) * 132 + col]) =
            make_float2(acc[nt][2] + bx, acc[nt][3] + by);
    }
    __syncthreads();

    for (int i = tid; i < 2048; i += 256) {
        int r = i >> 5, c = i & 31;
        if (row0 + r < Nrows) {
            float4 v = *reinterpret_cast<const float4*>(&stage[r * 132 + c * 4]);
            reinterpret_cast<float4*>(Yf)[(size_t)(row0 + r) * 32 + c] = v;
        }
    }
}

// ---------------------------------------------------------------------------
// Persistent fused GIN MLP: out = relu(relu(P @ W0^T + b0) @ W1^T + b1)
// grid = #SMs, 1 CTA/SM, 256 threads.
// Dyn smem 208896 B:
//   A0h[0) A0l[17408) A1h[34816) A1l[52224)
//   W0 [69632, 139264)   W1 [139264, 208896)   (each: hi 34816 | lo 34816)
// A double-buffered via cp.async; tmp staged into the consumed A buffer.
// ---------------------------------------------------------------------------
__global__ void __launch_bounds__(256, 1)
gin_mlp(const __nv_bfloat16* __restrict__ Ph, const __nv_bfloat16* __restrict__ Pl,
        const unsigned char* __restrict__ w0img, const unsigned char* __restrict__ w1img,
        const float* __restrict__ b0, const float* __restrict__ b1,
        float* __restrict__ Yf)
{
    extern __shared__ char sm[];
    const unsigned smb = smem_u32(sm);

    __shared__ float s_b0[128], s_b1[128];

    const int tid  = threadIdx.x;
    const int wid  = tid >> 5;
    const int lane = tid & 31;

    if (tid < 128) { s_b0[tid] = b0[tid]; s_b1[tid] = b1[tid]; }

    // --- preamble: async-copy W0, W1, and first A tile ---
    {
        const char* w0 = (const char*)w0img;
        const char* w1 = (const char*)w1img;
        for (int i = tid; i < 4352; i += 256) {
            cpa16(smb + 69632u  + i * 16, w0 + i * 16);
            cpa16(smb + 139264u + i * 16, w1 + i * 16);
        }
    }
    int t0 = blockIdx.x;
    {
        int row0 = t0 * 64;
        for (int i = tid; i < 1024; i += 256) {
            int r = i >> 4, c = i & 15;
            int row = row0 + r;
            bool ok = (row < NN);
            const char* srch = (const char*)(Ph + (size_t)(ok ? row : 0) * 128) + c * 16;
            const char* srcl = (const char*)(Pl + (size_t)(ok ? row : 0) * 128) + c * 16;
            unsigned d = (unsigned)(r * W_PITCH + c * 16);
            cpa16p(smb + d,          srch, ok);
            cpa16p(smb + 17408u + d, srcl, ok);
        }
    }
    CPA_COMMIT();
    CPA_WAIT0();
    __syncthreads();

    const int wr = (wid & 3) * 16;
    const int wc = (wid >> 2) * 64;
    const int grp = lane >> 2;
    const int tig = lane & 3;

    const unsigned aFragOff = (unsigned)(wr + (lane & 15)) * W_PITCH
                            + (unsigned)(((lane >> 4) & 1) * 16);
    const unsigned bRowOff  = (unsigned)((((lane >> 4) & 1) * 8 + (lane & 7)) * W_PITCH
                                         + ((lane >> 3) & 1) * 16);
    const unsigned b0H = smb + 69632u  + (unsigned)wc * W_PITCH + bRowOff;
    const unsigned b1H = smb + 139264u + (unsigned)wc * W_PITCH + bRowOff;

    int cur = 0;
    for (int t = t0; t < NT_TILES; t += gridDim.x) {
        const unsigned abuf = smb + (unsigned)cur * 34816u;
        const int tn = t + gridDim.x;

        // prefetch next A tile into alternate buffer
        if (tn < NT_TILES) {
            unsigned alt = smb + (unsigned)(cur ^ 1) * 34816u;
            int row0n = tn * 64;
            for (int i = tid; i < 1024; i += 256) {
                int r = i >> 4, c = i & 15;
                int row = row0n + r;
                bool ok = (row < NN);
                const char* srch = (const char*)(Ph + (size_t)(ok ? row : 0) * 128) + c * 16;
                const char* srcl = (const char*)(Pl + (size_t)(ok ? row : 0) * 128) + c * 16;
                unsigned d = (unsigned)(r * W_PITCH + c * 16);
                cpa16p(alt + d,          srch, ok);
                cpa16p(alt + 17408u + d, srcl, ok);
            }
            CPA_COMMIT();
        }

        // ---- phase 1: tmp = relu(A @ W0^T + b0) ----
        float acc[8][4];
#pragma unroll
        for (int n = 0; n < 8; n++)
#pragma unroll
            for (int q = 0; q < 4; q++) acc[n][q] = 0.f;

        unsigned aH = abuf + aFragOff;
        unsigned aL = aH + 17408u;
#pragma unroll
        for (int ks = 0; ks < 8; ks++) {
            unsigned ah[4], al[4];
            LDSM4(ah, aH + ks * 32);
            LDSM4(al, aL + ks * 32);
#pragma unroll
            for (int np = 0; np < 4; np++) {
                unsigned bh[4], bl[4];
                unsigned boff = (unsigned)(np * 16 * W_PITCH + ks * 32);
                LDSM4(bh, b0H + boff);
                LDSM4(bl, b0H + 34816u + boff);
                MMA16816(acc[2 * np],     ah, bh[0], bh[1]);
                MMA16816(acc[2 * np],     ah, bl[0], bl[1]);
                MMA16816(acc[2 * np],     al, bh[0], bh[1]);
                MMA16816(acc[2 * np + 1], ah, bh[2], bh[3]);
                MMA16816(acc[2 * np + 1], ah, bl[2], bl[3]);
                MMA16816(acc[2 * np + 1], al, bh[2], bh[3]);
            }
        }
        __syncthreads();   // all phase-1 reads of abuf done

        // stage tmp (relu, bf16 split) into abuf
#pragma unroll
        for (int nt = 0; nt < 8; nt++) {
            int col = wc + nt * 8 + tig * 2;
            float v00 = fmaxf(acc[nt][0] + s_b0[col],     0.f);
            float v01 = fmaxf(acc[nt][1] + s_b0[col + 1], 0.f);
            float v10 = fmaxf(acc[nt][2] + s_b0[col],     0.f);
            float v11 = fmaxf(acc[nt][3] + s_b0[col + 1], 0.f);
            __nv_bfloat162 h0, h1, l0, l1;
            h0.x = __float2bfloat16_rn(v00); h0.y = __float2bfloat16_rn(v01);
            h1.x = __float2bfloat16_rn(v10); h1.y = __float2bfloat16_rn(v11);
            l0.x = __float2bfloat16_rn(v00 - __bfloat162float(h0.x));
            l0.y = __float2bfloat16_rn(v01 - __bfloat162float(h0.y));
            l1.x = __float2bfloat16_rn(v10 - __bfloat162float(h1.x));
            l1.y = __float2bfloat16_rn(v11 - __bfloat162float(h1.y));
            unsigned dA = (unsigned)((wr + grp) * W_PITCH + col * 2);
            unsigned dB = (unsigned)((wr + grp + 8) * W_PITCH + col * 2);
            *reinterpret_cast<__nv_bfloat162*>(sm + (abuf - smb) + dA) = h0;
            *reinterpret_cast<__nv_bfloat162*>(sm + (abuf - smb) + dB) = h1;
            *reinterpret_cast<__nv_bfloat162*>(sm + (abuf - smb) + 17408u + dA) = l0;
            *reinterpret_cast<__nv_bfloat162*>(sm + (abuf - smb) + 17408u + dB) = l1;
        }
        __syncthreads();

        // ---- phase 2: out = relu(tmp @ W1^T + b1) ----
#pragma unroll
        for (int n = 0; n < 8; n++)
#pragma unroll
            for (int q = 0; q < 4; q++) acc[n][q] = 0.f;

#pragma unroll
        for (int ks = 0; ks < 8; ks++) {
            unsigned ah[4], al[4];
            LDSM4(ah, aH + ks * 32);
            LDSM4(al, aL + ks * 32);
#pragma unroll
            for (int np = 0; np < 4; np++) {
                unsigned bh[4], bl[4];
                unsigned boff = (unsigned)(np * 16 * W_PITCH + ks * 32);
                LDSM4(bh, b1H + boff);
                LDSM4(bl, b1H + 34816u + boff);
                MMA16816(acc[2 * np],     ah, bh[0], bh[1]);
                MMA16816(acc[2 * np],     ah, bl[0], bl[1]);
                MMA16816(acc[2 * np],     al, bh[0], bh[1]);
                MMA16816(acc[2 * np + 1], ah, bh[2], bh[3]);
                MMA16816(acc[2 * np + 1], ah, bl[2], bl[3]);
                MMA16816(acc[2 * np + 1], al, bh[2], bh[3]);
            }
        }

        // direct store (each 4-lane group fills a 32B sector)
        {
            int rowA = t * 64 + wr + grp;
            int rowB = rowA + 8;
#pragma unroll
            for (int nt = 0; nt < 8; nt++) {
                int col = wc + nt * 8 + tig * 2;
                float bx = s_b1[col], by = s_b1[col + 1];
                if (rowA < NN) {
                    float2 v = make_float2(fmaxf(acc[nt][0] + bx, 0.f),
                                           fmaxf(acc[nt][1] + by, 0.f));
                    *reinterpret_cast<float2*>(&Yf[(size_t)rowA * 128 + col]) = v;
                }
                if (rowB < NN) {
                    float2 v = make_float2(fmaxf(acc[nt][2] + bx, 0.f),
                                           fmaxf(acc[nt][3] + by, 0.f));
                    *reinterpret_cast<float2*>(&Yf[(size_t)rowB * 128 + col]) = v;
                }
            }
        }

        if (tn < NT_TILES) CPA_WAIT0();
        __syncthreads();
        cur ^= 1;
    }
}

// ---------------------------------------------------------------------------
// CSR build: degree count -> block scan -> fill
// ---------------------------------------------------------------------------
__global__ void count_deg(const int* __restrict__ ei, int* __restrict__ deg)
{
    int e = blockIdx.x * blockDim.x + threadIdx.x;
    if (e < NE) atomicAdd(&deg[ei[e]], 1);
}

#define SCAN_B 512
__global__ void scan1(const int* __restrict__ deg, int* __restrict__ rowptr,
                      int* __restrict__ bsums)
{
    __shared__ int sh[SCAN_B];
    int tid = threadIdx.x;
    int i = blockIdx.x * SCAN_B + tid;
    int v = (i < NN) ? deg[i] : 0;
    sh[tid] = v;
    __syncthreads();
#pragma unroll
    for (int off = 1; off < SCAN_B; off <<= 1) {
        int t = (tid >= off) ? sh[tid - off] : 0;
        __syncthreads();
        sh[tid] += t;
        __syncthreads();
    }
    if (i < NN) rowptr[i] = sh[tid] - v;
    if (tid == SCAN_B - 1) bsums[blockIdx.x] = sh[tid];
}

__global__ void scan2(int* __restrict__ bsums, int nb)
{
    __shared__ int sh[256];
    int tid = threadIdx.x;
    int v = (tid < nb) ? bsums[tid] : 0;
    sh[tid] = v;
    __syncthreads();
#pragma unroll
    for (int off = 1; off < 256; off <<= 1) {
        int t = (tid >= off) ? sh[tid - off] : 0;
        __syncthreads();
        sh[tid] += t;
        __syncthreads();
    }
    if (tid < nb) bsums[tid] = sh[tid] - v;
}

__global__ void scan3(int* __restrict__ rowptr, const int* __restrict__ bsums,
                      int* __restrict__ cursor)
{
    int i = blockIdx.x * SCAN_B + threadIdx.x;
    if (i < NN) {
        int r = rowptr[i] + bsums[blockIdx.x];
        rowptr[i] = r;
        cursor[i] = r;
    }
    if (i == 0) rowptr[NN] = NE;
}

__global__ void fill_csr(const int* __restrict__ ei, const float* __restrict__ mask,
                         int* __restrict__ cursor, int* __restrict__ csr_src,
                         float* __restrict__ csr_mask)
{
    int e = blockIdx.x * blockDim.x + threadIdx.x;
    if (e >= NE) return;
    int dst = ei[e];
    int src = ei[NE + e];
    int p = atomicAdd(&cursor[dst], 1);
    csr_src[p]  = src;
    csr_mask[p] = mask[e];
}

// ---------------------------------------------------------------------------
// pooled[n] = sum_{e in CSR(n)} mask_e * h[src_e] + (1+eps[l]) * h[n]
// Output written directly as bf16 hi/lo split (feeds the fused MLP).
// ---------------------------------------------------------------------------
__global__ void aggregate(const float* __restrict__ h, const int* __restrict__ rowptr,
                          const int* __restrict__ csr_src, const float* __restrict__ csr_mask,
                          const float* __restrict__ eps, int l,
                          __nv_bfloat16* __restrict__ ph, __nv_bfloat16* __restrict__ pl)
{
    int g = (blockIdx.x * blockDim.x + threadIdx.x) >> 5;
    int lane = threadIdx.x & 31;
    if (g >= NN) return;
    int beg = rowptr[g];
    int end = rowptr[g + 1];
    const float4* h4 = reinterpret_cast<const float4*>(h);

    float4 acc = make_float4(0.f, 0.f, 0.f, 0.f);
    int j = beg;
    for (; j + 1 < end; j += 2) {
        int   s0 = csr_src[j],   s1 = csr_src[j + 1];
        float m0 = csr_mask[j],  m1 = csr_mask[j + 1];
        float4 v0 = h4[(size_t)s0 * 32 + lane];
        float4 v1 = h4[(size_t)s1 * 32 + lane];
        acc.x += m0 * v0.x + m1 * v1.x;
        acc.y += m0 * v0.y + m1 * v1.y;
        acc.z += m0 * v0.z + m1 * v1.z;
        acc.w += m0 * v0.w + m1 * v1.w;
    }
    if (j < end) {
        int s0 = csr_src[j];
        float m0 = csr_mask[j];
        float4 v0 = h4[(size_t)s0 * 32 + lane];
        acc.x += m0 * v0.x; acc.y += m0 * v0.y;
        acc.z += m0 * v0.z; acc.w += m0 * v0.w;
    }
    float s = 1.f + eps[l];
    float4 hv4 = h4[(size_t)g * 32 + lane];
    acc.x += s * hv4.x; acc.y += s * hv4.y;
    acc.z += s * hv4.z; acc.w += s * hv4.w;

    __nv_bfloat162 hp0, hp1, lp0, lp1;
    hp0.x = __float2bfloat16_rn(acc.x);
    hp0.y = __float2bfloat16_rn(acc.y);
    hp1.x = __float2bfloat16_rn(acc.z);
    hp1.y = __float2bfloat16_rn(acc.w);
    lp0.x = __float2bfloat16_rn(acc.x - __bfloat162float(hp0.x));
    lp0.y = __float2bfloat16_rn(acc.y - __bfloat162float(hp0.y));
    lp1.x = __float2bfloat16_rn(acc.z - __bfloat162float(hp1.x));
    lp1.y = __float2bfloat16_rn(acc.w - __bfloat162float(hp1.y));
    uint2 hw, lw;
    hw.x = *reinterpret_cast<unsigned*>(&hp0);
    hw.y = *reinterpret_cast<unsigned*>(&hp1);
    lw.x = *reinterpret_cast<unsigned*>(&lp0);
    lw.y = *reinterpret_cast<unsigned*>(&lp1);
    reinterpret_cast<uint2*>(ph)[(size_t)g * 32 + lane] = hw;
    reinterpret_cast<uint2*>(pl)[(size_t)g * 32 + lane] = lw;
}

// pooled_sum[g] += sum over 5 embeds of nodes in graph g (batch is sorted)
__global__ void pool_batch(const float* __restrict__ embs, const int* __restrict__ batch,
                           float* __restrict__ ps)
{
    const int j = threadIdx.x;
    const int start = blockIdx.x * 128;
    int end = start + 128;
    if (end > NN) end = NN;
    if (start >= NN) return;

    const size_t EMB = (size_t)NN * DH;
    int gc = batch[start];
    float acc = 0.f;
    for (int i = start; i < end; i++) {
        int g = batch[i];
        if (g != gc) {
            atomicAdd(&ps[(size_t)gc * 128 + j], acc);
            acc = 0.f;
            gc = g;
        }
        size_t off = (size_t)i * 128 + j;
        float s = embs[off] + embs[EMB + off] + embs[2 * EMB + off]
                + embs[3 * EMB + off] + embs[4 * EMB + off];
        acc += s;
    }
    atomicAdd(&ps[(size_t)gc * 128 + j], acc);
}

// Head: lin1 = relu(ps @ W1^T + b1); lin1d = lin1; lin2 = lin1 @ W2^T + b2; softmax
__global__ void head(const float* __restrict__ ps,
                     const float* __restrict__ W1, const float* __restrict__ b1,
                     const float* __restrict__ W2, const float* __restrict__ b2,
                     float* __restrict__ lin1, float* __restrict__ lin1d,
                     float* __restrict__ lin2, float* __restrict__ soft)
{
    __shared__ float row[128];
    __shared__ float l1s[128];
    __shared__ float l2s[8];
    const int g = blockIdx.x;
    const int j = threadIdx.x;

    row[j] = ps[(size_t)g * 128 + j];
    __syncthreads();

    float a = b1[j];
#pragma unroll 8
    for (int k = 0; k < 128; k++) a += row[k] * W1[j * 128 + k];
    a = fmaxf(a, 0.f);
    l1s[j] = a;
    lin1[(size_t)g * 128 + j] = a;
    lin1d[(size_t)g * 128 + j] = a;
    __syncthreads();

    if (j < 8) {
        float s = b2[j];
#pragma unroll 8
        for (int k = 0; k < 128; k++) s += l1s[k] * W2[j * 128 + k];
        lin2[(size_t)g * 8 + j] = s;
        l2s[j] = s;
    }
    __syncthreads();
    if (j == 0) {
        float mx = l2s[0];
#pragma unroll
        for (int q = 1; q < 8; q++) mx = fmaxf(mx, l2s[q]);
        float ex[8]; float sum = 0.f;
#pragma unroll
        for (int q = 0; q < 8; q++) { ex[q] = expf(l2s[q] - mx); sum += ex[q]; }
        float inv = 1.f / sum;
#pragma unroll
        for (int q = 0; q < 8; q++) soft[(size_t)g * 8 + q] = ex[q] * inv;
    }
}

extern "C" void kernel_launch(void* const* d_in, const int* in_sizes, int n_in,
                              void* d_out, int out_size)
{
    const float* x     = (const float*)d_in[0];
    const int*   ei    = (const int*)  d_in[1];
    const float* mask  = (const float*)d_in[2];
    const int*   batch = (const int*)  d_in[3];
    const float* eps   = (const float*)d_in[4];
    const float* Wf    = (const float*)d_in[5];
    const float* bf    = (const float*)d_in[6];
    const float* gW    = (const float*)d_in[7];   // [4][2][128][128]
    const float* gb    = (const float*)d_in[8];   // [4][2][128]
    const float* W1    = (const float*)d_in[9];
    const float* b1    = (const float*)d_in[10];
    const float* W2    = (const float*)d_in[11];
    const float* b2    = (const float*)d_in[12];

    float* out  = (float*)d_out;
    const size_t EMB = (size_t)NN * DH;
    float* embs = out;                       // [5][NN][128]
    float* ps   = out + 5 * EMB;             // [256][128]
    float* l1   = ps + (size_t)NG * DH;
    float* l1d  = l1 + (size_t)NG * DH;
    float* l2   = l1d + (size_t)NG * DH;
    float* sm   = l2 + (size_t)NG * DOUT;

    float* csr_mask = nullptr;
    int *deg = nullptr, *rowptr = nullptr, *cursor = nullptr, *bsums = nullptr, *csr_src = nullptr;
    unsigned char* wimg = nullptr;
    __nv_bfloat16 *xh = nullptr, *xl = nullptr, *ph = nullptr, *pl = nullptr;
    cudaGetSymbolAddress((void**)&deg,      g_deg);
    cudaGetSymbolAddress((void**)&rowptr,   g_rowptr);
    cudaGetSymbolAddress((void**)&cursor,   g_cursor);
    cudaGetSymbolAddress((void**)&bsums,    g_bsums);
    cudaGetSymbolAddress((void**)&csr_src,  g_csr_src);
    cudaGetSymbolAddress((void**)&csr_mask, g_csr_mask);
    cudaGetSymbolAddress((void**)&wimg,     g_wimg);
    cudaGetSymbolAddress((void**)&xh,       g_xh);
    cudaGetSymbolAddress((void**)&xl,       g_xl);
    cudaGetSymbolAddress((void**)&ph,       g_ph);
    cudaGetSymbolAddress((void**)&pl,       g_pl);

    int nsm = 148;
    cudaDeviceGetAttribute(&nsm, cudaDevAttrMultiProcessorCount, 0);

    const int GEMM_SMEM = 104448;
    const int MLP_SMEM  = 208896;
    cudaFuncSetAttribute(gemm64,  cudaFuncAttributeMaxDynamicSharedMemorySize, GEMM_SMEM);
    cudaFuncSetAttribute(gin_mlp, cudaFuncAttributeMaxDynamicSharedMemorySize, MLP_SMEM);

    const int GEMM_BLOCKS = NT_TILES;                    // 1563
    const int SCAN_BLOCKS = (NN + SCAN_B - 1) / SCAN_B;  // 196
    const int EDGE_BLOCKS = (NE + 255) / 256;
    const int AGG_BLOCKS  = (NN * 32 + 255) / 256;
    const int POOL_BLOCKS = (NN + 127) / 128;
    const int SPLIT_BLOCKS = (NN * DH / 8 + 255) / 256;

    cudaMemsetAsync(ps, 0, (size_t)NG * DH * sizeof(float), 0);
    cudaMemsetAsync(deg, 0, (size_t)NN * sizeof(int), 0);

    prep_weights<<<9, 256>>>(Wf, gW, wimg);
    split_x<<<SPLIT_BLOCKS, 256>>>(x, xh, xl);
    count_deg<<<EDGE_BLOCKS, 256>>>(ei, deg);
    scan1<<<SCAN_BLOCKS, SCAN_B>>>(deg, rowptr, bsums);
    scan2<<<1, 256>>>(bsums, SCAN_BLOCKS);
    scan3<<<SCAN_BLOCKS, SCAN_B>>>(rowptr, bsums, cursor);
    fill_csr<<<EDGE_BLOCKS, 256>>>(ei, mask, cursor, csr_src, csr_mask);

    // first linear (NO relu) -> embs[0] fp32
    gemm64<<<GEMM_BLOCKS, 256, GEMM_SMEM>>>(xh, xl, wimg, bf, embs, NN);

    for (int l = 0; l < NLAYERS; l++) {
        const float* h = embs + (size_t)l * EMB;
        aggregate<<<AGG_BLOCKS, 256>>>(h, rowptr, csr_src, csr_mask, eps, l, ph, pl);
        gin_mlp<<<nsm, 256, MLP_SMEM>>>(
            ph, pl,
            wimg + (size_t)(1 + l * 2 + 0) * W_STRIDE,
            wimg + (size_t)(1 + l * 2 + 1) * W_STRIDE,
            gb + (size_t)(l * 2 + 0) * 128, gb + (size_t)(l * 2 + 1) * 128,
            embs + (size_t)(l + 1) * EMB);
    }

    pool_batch<<<POOL_BLOCKS, 128>>>(embs, batch, ps);
    head<<<NG, 128>>>(ps, W1, b1, W2, b2, l1, l1d, l2, sm);
}